// round 12
// baseline (speedup 1.0000x reference)
#include <cuda_runtime.h>
#include <cuda_bf16.h>
#include <mma.h>
#include <cstdint>

using namespace nvcuda;

// ---------------- problem constants ----------------
#define BATCH   16384
#define KMER    17
#define HH      136
#define LL      272
#define GATES   544
#define GCOLS   1088
#define NL      3
#define OUTC    16
#define NCAPS   10
#define KCAT    408           // 272 + 136 concatenated K

// ---------------- device scratch --------------------------------------------
__device__ __align__(256) __nv_bfloat16 g_Xb0[(size_t)BATCH * 2 * LL];
__device__ __align__(256) __nv_bfloat16 g_Xb1[(size_t)BATCH * 2 * LL];
__device__ __align__(256) float         g_Cf [(size_t)BATCH * HH];
__device__ __align__(256) float         g_Cb [(size_t)BATCH * HH];
__device__ __align__(256) __nv_bfloat16 g_Wcat[(size_t)NL * 2 * GATES * KCAT];
__device__ __align__(256) float         g_Bs [(size_t)NL * GCOLS];
__device__ __align__(256) __nv_bfloat16 g_Wcb[(size_t)NCAPS * OUTC * LL];

// ---------------- fast transcendentals (MUFU tanh, sm_75+) -------------------
__device__ __forceinline__ float fast_tanh(float x) {
    float r;
    asm("tanh.approx.f32 %0, %1;" : "=f"(r) : "f"(x));
    return r;
}
__device__ __forceinline__ float fast_sigm(float x) {
    return fmaf(fast_tanh(0.5f * x), 0.5f, 0.5f);
}
__device__ __forceinline__ float sigm(float x) { return 1.f / (1.f + expf(-x)); }

__device__ __forceinline__ uint32_t smem_u32(const void* p) {
    uint32_t a;
    asm("{ .reg .u64 t; cvta.to.shared.u64 t, %1; cvt.u32.u64 %0, t; }" : "=r"(a) : "l"(p));
    return a;
}
__device__ __forceinline__ void cp16(uint32_t smaddr, const void* g, int sb) {
    asm volatile("cp.async.cg.shared.global [%0], [%1], 16, %2;\n"
                 :: "r"(smaddr), "l"(g), "r"(sb));
}
__device__ __forceinline__ void cp_wait_n(int n) {
    if (n <= 0)      asm volatile("cp.async.wait_group 0;");
    else if (n == 1) asm volatile("cp.async.wait_group 1;");
    else             asm volatile("cp.async.wait_group 2;");
}

// ---------------- setup kernel 1: layer-0 input ------------------------------
__global__ void prep_kernel(const int* __restrict__ seq,
                            const float* __restrict__ sig,
                            const float* __restrict__ embed,
                            __nv_bfloat16* __restrict__ X)
{
    int idx = blockIdx.x * blockDim.x + threadIdx.x;
    if (idx >= BATCH * LL) return;
    int b = idx / LL, r = idx % LL;
    int p = r >> 4, e = r & 15;
    int tok = seq[b * KMER + p];
    X[(size_t)b * 544 + r]       = __float2bfloat16(embed[tok * 16 + e]);
    X[(size_t)b * 544 + 272 + r] = __float2bfloat16(sig[(size_t)b * LL + r]);
}

// ---------------- setup kernel 2: all weight conversions ---------------------
__global__ void weights_kernel(const float* __restrict__ wih,
                               const float* __restrict__ whh,
                               const float* __restrict__ bih,
                               const float* __restrict__ bhh,
                               const float* __restrict__ wcaps,
                               __nv_bfloat16* __restrict__ wcat,
                               float* __restrict__ bsum,
                               __nv_bfloat16* __restrict__ wcb)
{
    const int nW = NL * 2 * GATES * KCAT;     // 1331712
    const int nB = NL * GCOLS;                // 3264
    const int nC = NCAPS * OUTC * LL;         // 43520
    int i = blockIdx.x * blockDim.x + threadIdx.x;

    if (i < nW) {
        const int per = GATES * KCAT;
        int ld = i / per;  int r = i % per;
        int n = r / KCAT, k = r % KCAT;
        int j = n >> 2, g = n & 3;
        float v = (k < 272)
            ? wih[((size_t)ld * GATES + g * HH + j) * LL + k]
            : whh[((size_t)ld * GATES + g * HH + j) * HH + (k - 272)];
        wcat[i] = __float2bfloat16(v);
        return;
    }
    i -= nW;
    if (i < nB) {
        int l = i / GCOLS; int np = i % GCOLS;
        int d = np / GATES, q = np % GATES;
        int j = q >> 2, g = q & 3;
        int src = (l * 2 + d) * GATES + g * HH + j;
        bsum[i] = bih[src] + bhh[src];
        return;
    }
    i -= nB;
    if (i < nC) wcb[i] = __float2bfloat16(wcaps[i]);
}

// ---------------- templated, fully unrolled MMA step for one 64-K stage ------
template<int VJ>
__device__ __forceinline__ void mma_stage(const __nv_bfloat16* __restrict__ Ab,
                                          const __nv_bfloat16* __restrict__ Bb,
                                          int wm0, int wn0,
                                          wmma::fragment<wmma::accumulator, 16, 16, 16, float> (&acc)[2][4])
{
    #pragma unroll
    for (int ks = 0; ks < 4; ++ks) {
        const int kk = ks * 16;
        wmma::fragment<wmma::matrix_a, 16, 16, 16, __nv_bfloat16, wmma::row_major> af[2];
        wmma::fragment<wmma::matrix_b, 16, 16, 16, __nv_bfloat16, wmma::col_major> bfr[VJ];
        #pragma unroll
        for (int i = 0; i < 2; ++i)
            wmma::load_matrix_sync(af[i], Ab + (wm0 + i * 16) * 72 + kk, 72);
        #pragma unroll
        for (int j = 0; j < VJ; ++j)
            wmma::load_matrix_sync(bfr[j], Bb + (wn0 + j * 16) * 72 + kk, 72);
        #pragma unroll
        for (int i = 0; i < 2; ++i)
            #pragma unroll
            for (int j = 0; j < VJ; ++j)
                wmma::mma_sync(acc[i][j], af[i], bfr[j], acc[i][j]);
    }
}

// ---------------- fused LSTM GEMM (wmma bf16, NT, 3-stage pipeline) ----------
// Block tile 128x128, BK=64, 8 warps (32x64 each). z = blockIdx.z = direction.
// MODE 0: gates_first = x_first @ Wih^T + b ; cell1 (c_prev=0) -> h, C.
// MODE 1: gates_second = [x_second | h_first] @ Wcat^T + b ; cell2 -> h.
template<int KACT, int MODE>
__global__ __launch_bounds__(256)
void gemm_lstm(const __nv_bfloat16* __restrict__ Xc,
               const __nv_bfloat16* __restrict__ Wcat,
               const float* __restrict__ bsum,
               __nv_bfloat16* __restrict__ Xn,
               float* __restrict__ Cf, float* __restrict__ Cb)
{
    extern __shared__ __align__(16) char dsm[];
    const int STG = 128 * 72 * 2;          // 18432 B per stage per matrix

    const int tid   = threadIdx.x;
    const int warpI = tid >> 5;
    const int lane  = tid & 31;
    const int z     = blockIdx.z;
    const int bm0   = blockIdx.y * 128;
    const int bn0   = blockIdx.x * 128;
    const int wm0   = (warpI & 3) * 32;
    const int wn0   = (warpI >> 2) * 64;

    const uint32_t smA = smem_u32(dsm);
    const uint32_t smB = smA + 3 * STG;

    const __nv_bfloat16* A1 = Xc + (MODE == 0 ? z * 272 : (1 - z) * 272);
    const __nv_bfloat16* A2 = Xn + z * 408;
    const __nv_bfloat16* Bsrc = Wcat + (size_t)z * GATES * KCAT;

    // valid 16-col fragments for this warp: 4 (full), 2 (tail CTA wn0=0), 0
    const int cgBase = bn0 + wn0;
    const int vj = (cgBase + 64 <= GATES) ? 4
                 : (cgBase < GATES ? (GATES - cgBase) >> 4 : 0);   // 544-512=32 -> 2

    wmma::fragment<wmma::accumulator, 16, 16, 16, float> acc[2][4];
    #pragma unroll
    for (int i = 0; i < 2; ++i)
        #pragma unroll
        for (int j = 0; j < 4; ++j)
            wmma::fill_fragment(acc[i][j], 0.0f);

    const int nS = (KACT + 63) >> 6;

    auto load_stage = [&](int s, int buf) {
        const int k0 = s * 64;
        #pragma unroll
        for (int it = 0; it < 4; ++it) {
            int c   = tid + it * 256;
            int row = c >> 3;
            int kc  = (c & 7) * 8;
            int kg  = k0 + kc;
            bool kv = kg < KACT;
            const __nv_bfloat16* ap;
            if (MODE == 0 || kg < 272)
                ap = A1 + (size_t)(bm0 + row) * 544 + (kv ? kg : 0);
            else
                ap = A2 + (size_t)(bm0 + row) * 544 + (kv ? (kg - 272) : 0);
            cp16(smA + buf * STG + row * 144 + kc * 2, ap, kv ? 16 : 0);
            int n   = bn0 + row;
            bool bok = kv && (n < GATES);
            const __nv_bfloat16* bp = Bsrc + (size_t)(n < GATES ? n : 0) * KCAT
                                           + (kv ? kg : 0);
            cp16(smB + buf * STG + row * 144 + kc * 2, bp, bok ? 16 : 0);
        }
        asm volatile("cp.async.commit_group;\n");
    };

    load_stage(0, 0);
    if (nS > 1) load_stage(1, 1);

    for (int s = 0; s < nS; ++s) {
        if (s + 2 < nS) load_stage(s + 2, (s + 2) % 3);
        cp_wait_n(nS - 1 - s < 2 ? nS - 1 - s : 2);
        __syncthreads();

        const int buf = s % 3;
        const __nv_bfloat16* Ab = reinterpret_cast<const __nv_bfloat16*>(dsm) + buf * (128 * 72);
        const __nv_bfloat16* Bb = reinterpret_cast<const __nv_bfloat16*>(dsm + 3 * STG) + buf * (128 * 72);

        if (vj == 4)      mma_stage<4>(Ab, Bb, wm0, wn0, acc);
        else if (vj == 2) mma_stage<2>(Ab, Bb, wm0, wn0, acc);
        // vj == 0: no MMA work; still hit the barriers below
        __syncthreads();
    }

    // ---- fused LSTM epilogue (MUFU tanh) ------------------------------------
    float* stageW = reinterpret_cast<float*>(dsm) + warpI * 320;
    const int rr = lane >> 1;
    const int cc = (lane & 1) * 8;

    const float* bs = bsum + z * 544;
    float* Csel = z ? Cb : Cf;
    const int hoff = (MODE == 0) ? (z ? 408 : 0) : (z ? 136 : 272);

    #pragma unroll
    for (int i = 0; i < 2; ++i) {
        #pragma unroll
        for (int j = 0; j < 4; ++j) {
            if (j >= vj) continue;       // uniform per warp; frags beyond vj unused
            const int cg0 = cgBase + j * 16;
            wmma::store_matrix_sync(stageW, acc[i][j], 20, wmma::mem_row_major);
            __syncwarp();

            const int b  = bm0 + wm0 + i * 16 + rr;
            const int gc = cg0 + cc;
            float4 v0 = *reinterpret_cast<float4*>(&stageW[rr * 20 + cc]);
            float4 v1 = *reinterpret_cast<float4*>(&stageW[rr * 20 + cc + 4]);
            __syncwarp();

            const float4 b0 = *reinterpret_cast<const float4*>(bs + gc);
            const float4 b1 = *reinterpret_cast<const float4*>(bs + gc + 4);

            #pragma unroll
            for (int q = 0; q < 2; ++q) {
                float4 v  = q ? v1 : v0;
                float4 bb = q ? b1 : b0;
                int j2 = ((gc + q * 4) >> 2);
                float gi = v.x + bb.x;
                float gf = v.y + bb.y;
                float gg = v.z + bb.z;
                float go = v.w + bb.w;
                float c;
                if (MODE == 0) c = fast_sigm(gi) * fast_tanh(gg);
                else           c = fast_sigm(gf) * Csel[(size_t)b * HH + j2]
                                 + fast_sigm(gi) * fast_tanh(gg);
                float h = fast_sigm(go) * fast_tanh(c);
                if (MODE == 0) Csel[(size_t)b * HH + j2] = c;
                Xn[(size_t)b * 544 + hoff + j2] = __float2bfloat16(h);
            }
        }
    }
}

// ---------------- fused head: cooperative, vectorized u_hat -----------------
#define EPB 4
__global__ __launch_bounds__(128 * EPB)
void head_kernel(const __nv_bfloat16* __restrict__ X,
                 const float* __restrict__ conv_w,
                 const float* __restrict__ conv_b,
                 const __nv_bfloat16* __restrict__ Wcb,
                 const float* __restrict__ fc1_w,
                 const float* __restrict__ fc1_b,
                 const float* __restrict__ fc2_w,
                 const float* __restrict__ fc2_b,
                 float* __restrict__ out, int out_size)
{
    extern __shared__ float hsm[];
    float* xs_a    = hsm;
    float* u_a     = xs_a + EPB * 2 * LL;
    float* sred_a  = u_a + EPB * NCAPS * LL;
    float* scale_a = sred_a + EPB * NCAPS * 4;
    float* uhat_a  = scale_a + EPB * NCAPS;
    float* vv_a    = uhat_a + EPB * NCAPS * OUTC;
    float* wred_a  = vv_a + EPB * OUTC;

    const int tid  = threadIdx.x;
    const int e    = tid >> 7;
    const int t    = tid & 127;
    const int lane = tid & 31;
    const int W16  = tid >> 5;
    const int w4   = W16 & 3;
    const int b    = blockIdx.x * EPB + e;
    const __nv_bfloat16* x = X + (size_t)b * 544;

    float* xs    = xs_a    + e * 2 * LL;
    float* u     = u_a     + e * NCAPS * LL;
    float* scale = scale_a + e * NCAPS;
    float* vv    = vv_a    + e * OUTC;
    float* wred  = wred_a  + e * 8;

    for (int i = t; i < 544; i += 128)
        xs[i] = __bfloat162float(x[i]);
    __syncthreads();

    for (int idx = t; idx < NCAPS * LL; idx += 128) {
        int c = idx / LL, k = idx % LL;
        int dd = (c >> 1) + 1, o = c & 1;
        int left = dd >> 1;
        const float* w = conv_w + (size_t)((dd - 1) * 2 + o) * 4;
        float acc = conv_b[(dd - 1) * 2 + o];
        #pragma unroll
        for (int i = 0; i < 2; ++i)
            #pragma unroll
            for (int kk = 0; kk < 2; ++kk) {
                int p = k + kk * dd - left;
                if (p >= 0 && p < LL) acc += w[i * 2 + kk] * xs[i * LL + p];
            }
        u[c * LL + k] = acc;
    }
    __syncthreads();

    #pragma unroll
    for (int c = 0; c < NCAPS; ++c) {
        float q0 = u[c * LL + t];
        float q1 = u[c * LL + t + 128];
        float p  = q0 * q0 + q1 * q1;
        if (t < 16) { float q2 = u[c * LL + t + 256]; p += q2 * q2; }
        #pragma unroll
        for (int off = 16; off > 0; off >>= 1)
            p += __shfl_down_sync(0xffffffffu, p, off);
        if (lane == 0) sred_a[(e * NCAPS + c) * 4 + w4] = p;
    }
    __syncthreads();
    if (t < NCAPS) {
        const float* sr = &sred_a[(e * NCAPS + t) * 4];
        float s2 = sr[0] + sr[1] + sr[2] + sr[3];
        float n = sqrtf(s2);
        scale[t] = (1.f - 1.f / (expf(n) + 1e-20f)) / (n + 1e-20f);
    }
    __syncthreads();

    // ---- u_hat: vectorized (bf16x2 W loads, float2 smem reads) ----
    for (int p = W16; p < NCAPS * OUTC; p += 16) {
        int c = p >> 4;
        const __nv_bfloat162* wr2 =
            reinterpret_cast<const __nv_bfloat162*>(Wcb + (size_t)p * LL);
        const float2* u0 = reinterpret_cast<const float2*>(u_a + 0 * NCAPS * LL + c * LL);
        const float2* u1 = reinterpret_cast<const float2*>(u_a + 1 * NCAPS * LL + c * LL);
        const float2* u2 = reinterpret_cast<const float2*>(u_a + 2 * NCAPS * LL + c * LL);
        const float2* u3 = reinterpret_cast<const float2*>(u_a + 3 * NCAPS * LL + c * LL);
        float a0 = 0.f, a1 = 0.f, a2 = 0.f, a3 = 0.f;
        #pragma unroll
        for (int s = 0; s < 5; ++s) {
            int kp = s * 32 + lane;
            if (kp < LL / 2) {
                float2 w2 = __bfloat1622float2(wr2[kp]);
                float2 q;
                q = u0[kp]; a0 += w2.x * q.x + w2.y * q.y;
                q = u1[kp]; a1 += w2.x * q.x + w2.y * q.y;
                q = u2[kp]; a2 += w2.x * q.x + w2.y * q.y;
                q = u3[kp]; a3 += w2.x * q.x + w2.y * q.y;
            }
        }
        #pragma unroll
        for (int off = 16; off > 0; off >>= 1) {
            a0 += __shfl_down_sync(0xffffffffu, a0, off);
            a1 += __shfl_down_sync(0xffffffffu, a1, off);
            a2 += __shfl_down_sync(0xffffffffu, a2, off);
            a3 += __shfl_down_sync(0xffffffffu, a3, off);
        }
        if (lane == 0) {
            uhat_a[0 * 160 + p] = a0 * scale_a[0 * NCAPS + c];
            uhat_a[1 * 160 + p] = a1 * scale_a[1 * NCAPS + c];
            uhat_a[2 * 160 + p] = a2 * scale_a[2 * NCAPS + c];
            uhat_a[3 * 160 + p] = a3 * scale_a[3 * NCAPS + c];
        }
    }
    __syncthreads();

    if (t < OUTC) {
        float s = 0.f;
        #pragma unroll
        for (int c = 0; c < NCAPS; ++c) s += uhat_a[e * 160 + c * OUTC + t];
        float sq = s * s;
        #pragma unroll
        for (int off = 8; off > 0; off >>= 1)
            sq += __shfl_xor_sync(0x0000ffffu, sq, off);
        float f = sq / (1.f + sq) / sqrtf(sq);
        vv[t] = f * s;
    }
    __syncthreads();

    float p0 = 0.f, p1 = 0.f;
    for (int j = t; j < HH; j += 128) {
        float h = fc1_b[j];
        #pragma unroll
        for (int o = 0; o < OUTC; ++o) h += vv[o] * fc1_w[j * OUTC + o];
        h = fmaxf(h, 0.f);
        p0 += fc2_w[j] * h;
        p1 += fc2_w[HH + j] * h;
    }
    #pragma unroll
    for (int off = 16; off > 0; off >>= 1) {
        p0 += __shfl_down_sync(0xffffffffu, p0, off);
        p1 += __shfl_down_sync(0xffffffffu, p1, off);
    }
    if (lane == 0) { wred[w4 * 2 + 0] = p0; wred[w4 * 2 + 1] = p1; }
    __syncthreads();

    if (t == 0) {
        float l0 = fc2_b[0], l1 = fc2_b[1];
        #pragma unroll
        for (int ww = 0; ww < 4; ++ww) { l0 += wred[ww * 2 + 0]; l1 += wred[ww * 2 + 1]; }
        out[(size_t)b * 2 + 0] = l0;
        out[(size_t)b * 2 + 1] = l1;
        if (out_size >= 4 * BATCH) {
            float m = fmaxf(l0, l1);
            float e0 = expf(l0 - m), e1 = expf(l1 - m);
            float den = e0 + e1;
            out[(size_t)2 * BATCH + b * 2 + 0] = e0 / den;
            out[(size_t)2 * BATCH + b * 2 + 1] = e1 / den;
        }
    }
}

// ---------------- launch ----------------------------------------------------
extern "C" void kernel_launch(void* const* d_in, const int* in_sizes, int n_in,
                              void* d_out, int out_size)
{
    const int*   seq    = (const int*)  d_in[0];
    const float* sig    = (const float*)d_in[1];
    const float* embed  = (const float*)d_in[2];
    const float* w_ih   = (const float*)d_in[3];
    const float* w_hh   = (const float*)d_in[4];
    const float* b_ih   = (const float*)d_in[5];
    const float* b_hh   = (const float*)d_in[6];
    const float* conv_w = (const float*)d_in[7];
    const float* conv_b = (const float*)d_in[8];
    const float* W_caps = (const float*)d_in[9];
    const float* fc1_w  = (const float*)d_in[10];
    const float* fc1_b  = (const float*)d_in[11];
    const float* fc2_w  = (const float*)d_in[12];
    const float* fc2_b  = (const float*)d_in[13];
    float* out = (float*)d_out;

    __nv_bfloat16 *X0, *X1, *Wcat, *Wcb;
    float *Cf, *Cb, *Bsum;
    cudaGetSymbolAddress((void**)&X0,   g_Xb0);
    cudaGetSymbolAddress((void**)&X1,   g_Xb1);
    cudaGetSymbolAddress((void**)&Cf,   g_Cf);
    cudaGetSymbolAddress((void**)&Cb,   g_Cb);
    cudaGetSymbolAddress((void**)&Wcat, g_Wcat);
    cudaGetSymbolAddress((void**)&Bsum, g_Bs);
    cudaGetSymbolAddress((void**)&Wcb,  g_Wcb);
    __nv_bfloat16* Xs[2] = {X0, X1};

    const int SMEM_G = 3 * 128 * 72 * 2 * 2;     // 110592
    const int SMEM_H = (EPB * (2*LL + NCAPS*LL + NCAPS*4 + NCAPS + NCAPS*OUTC + OUTC + 8)) * 4;
    cudaFuncSetAttribute(gemm_lstm<272, 0>,
                         cudaFuncAttributeMaxDynamicSharedMemorySize, SMEM_G);
    cudaFuncSetAttribute(gemm_lstm<408, 1>,
                         cudaFuncAttributeMaxDynamicSharedMemorySize, SMEM_G);
    cudaFuncSetAttribute(head_kernel,
                         cudaFuncAttributeMaxDynamicSharedMemorySize, SMEM_H);

    prep_kernel<<<(BATCH * LL + 255) / 256, 256>>>(seq, sig, embed, X0);

    const int nWtot = NL * 2 * GATES * KCAT + NL * GCOLS + NCAPS * OUTC * LL;
    weights_kernel<<<(nWtot + 255) / 256, 256>>>(w_ih, w_hh, b_ih, b_hh, W_caps,
                                                 Wcat, Bsum, Wcb);

    dim3 grid(5, BATCH / 128, 2);
    for (int l = 0; l < NL; ++l) {
        __nv_bfloat16* Xc = Xs[l & 1];
        __nv_bfloat16* Xn = Xs[(l + 1) & 1];
        const __nv_bfloat16* Wl = Wcat + (size_t)l * 2 * GATES * KCAT;
        const float* Bl = Bsum + (size_t)l * GCOLS;

        gemm_lstm<272, 0><<<grid, 256, SMEM_G>>>(Xc, Wl, Bl, Xn, Cf, Cb);
        gemm_lstm<408, 1><<<grid, 256, SMEM_G>>>(Xc, Wl, Bl, Xn, Cf, Cb);
    }

    head_kernel<<<BATCH / EPB, 128 * EPB, SMEM_H>>>(X1, conv_w, conv_b, Wcb,
                                                    fc1_w, fc1_b, fc2_w, fc2_b,
                                                    out, out_size);
}

// round 13
// speedup vs baseline: 1.1091x; 1.1091x over previous
#include <cuda_runtime.h>
#include <cuda_bf16.h>
#include <mma.h>
#include <cstdint>

using namespace nvcuda;

// ---------------- problem constants ----------------
#define BATCH   16384
#define KMER    17
#define HH      136
#define LL      272
#define GATES   544
#define GCOLS   1088
#define NL      3
#define OUTC    16
#define NCAPS   10
#define KCAT    408           // 272 + 136 concatenated K

// ---------------- device scratch --------------------------------------------
__device__ __align__(256) __nv_bfloat16 g_Xb0[(size_t)BATCH * 2 * LL];
__device__ __align__(256) __nv_bfloat16 g_Xb1[(size_t)BATCH * 2 * LL];
__device__ __align__(256) float         g_Cf [(size_t)BATCH * HH];
__device__ __align__(256) float         g_Cb [(size_t)BATCH * HH];
__device__ __align__(256) __nv_bfloat16 g_Wcat[(size_t)NL * 2 * GATES * KCAT];
__device__ __align__(256) float         g_Bs [(size_t)NL * GCOLS];
__device__ __align__(256) __nv_bfloat16 g_Wcb[(size_t)NCAPS * OUTC * LL];

// ---------------- fast transcendentals (MUFU tanh, sm_75+) -------------------
__device__ __forceinline__ float fast_tanh(float x) {
    float r;
    asm("tanh.approx.f32 %0, %1;" : "=f"(r) : "f"(x));
    return r;
}
__device__ __forceinline__ float fast_sigm(float x) {
    return fmaf(fast_tanh(0.5f * x), 0.5f, 0.5f);
}

__device__ __forceinline__ uint32_t smem_u32(const void* p) {
    uint32_t a;
    asm("{ .reg .u64 t; cvta.to.shared.u64 t, %1; cvt.u32.u64 %0, t; }" : "=r"(a) : "l"(p));
    return a;
}
__device__ __forceinline__ void cp16(uint32_t smaddr, const void* g, int sb) {
    asm volatile("cp.async.cg.shared.global [%0], [%1], 16, %2;\n"
                 :: "r"(smaddr), "l"(g), "r"(sb));
}
__device__ __forceinline__ void cp_wait_n(int n) {
    if (n <= 0)      asm volatile("cp.async.wait_group 0;");
    else if (n == 1) asm volatile("cp.async.wait_group 1;");
    else             asm volatile("cp.async.wait_group 2;");
}

// ---------------- setup kernel 1: layer-0 input ------------------------------
__global__ void prep_kernel(const int* __restrict__ seq,
                            const float* __restrict__ sig,
                            const float* __restrict__ embed,
                            __nv_bfloat16* __restrict__ X)
{
    int idx = blockIdx.x * blockDim.x + threadIdx.x;
    if (idx >= BATCH * LL) return;
    int b = idx / LL, r = idx % LL;
    int p = r >> 4, e = r & 15;
    int tok = seq[b * KMER + p];
    X[(size_t)b * 544 + r]       = __float2bfloat16(embed[tok * 16 + e]);
    X[(size_t)b * 544 + 272 + r] = __float2bfloat16(sig[(size_t)b * LL + r]);
}

// ---------------- setup kernel 2: all weight conversions ---------------------
__global__ void weights_kernel(const float* __restrict__ wih,
                               const float* __restrict__ whh,
                               const float* __restrict__ bih,
                               const float* __restrict__ bhh,
                               const float* __restrict__ wcaps,
                               __nv_bfloat16* __restrict__ wcat,
                               float* __restrict__ bsum,
                               __nv_bfloat16* __restrict__ wcb)
{
    const int nW = NL * 2 * GATES * KCAT;     // 1331712
    const int nB = NL * GCOLS;                // 3264
    const int nC = NCAPS * OUTC * LL;         // 43520
    int i = blockIdx.x * blockDim.x + threadIdx.x;

    if (i < nW) {
        const int per = GATES * KCAT;
        int ld = i / per;  int r = i % per;
        int n = r / KCAT, k = r % KCAT;
        int j = n >> 2, g = n & 3;
        float v = (k < 272)
            ? wih[((size_t)ld * GATES + g * HH + j) * LL + k]
            : whh[((size_t)ld * GATES + g * HH + j) * HH + (k - 272)];
        wcat[i] = __float2bfloat16(v);
        return;
    }
    i -= nW;
    if (i < nB) {
        int l = i / GCOLS; int np = i % GCOLS;
        int d = np / GATES, q = np % GATES;
        int j = q >> 2, g = q & 3;
        int src = (l * 2 + d) * GATES + g * HH + j;
        bsum[i] = bih[src] + bhh[src];
        return;
    }
    i -= nB;
    if (i < nC) wcb[i] = __float2bfloat16(wcaps[i]);
}

// ---------------- fused LSTM GEMM (wmma bf16, NT, 3-stage pipeline) ----------
// Block tile 128x128, BK=64, 8 warps (32x64 each). z = blockIdx.z = direction.
// __launch_bounds__(256, 2) pins regs <= 128 so 2 CTAs/SM always fit.
// MODE 0: gates_first = x_first @ Wih^T + b ; cell1 (c_prev=0) -> h, C.
// MODE 1: gates_second = [x_second | h_first] @ Wcat^T + b ; cell2 -> h.
template<int KACT, int MODE>
__global__ __launch_bounds__(256, 2)
void gemm_lstm(const __nv_bfloat16* __restrict__ Xc,
               const __nv_bfloat16* __restrict__ Wcat,
               const float* __restrict__ bsum,
               __nv_bfloat16* __restrict__ Xn,
               float* __restrict__ Cf, float* __restrict__ Cb)
{
    extern __shared__ __align__(16) char dsm[];
    const int STG = 128 * 72 * 2;          // 18432 B per stage per matrix

    const int tid   = threadIdx.x;
    const int warpI = tid >> 5;
    const int lane  = tid & 31;
    const int z     = blockIdx.z;
    const int bm0   = blockIdx.y * 128;
    const int bn0   = blockIdx.x * 128;
    const int wm0   = (warpI & 3) * 32;
    const int wn0   = (warpI >> 2) * 64;

    const uint32_t smA = smem_u32(dsm);
    const uint32_t smB = smA + 3 * STG;

    const __nv_bfloat16* A1 = Xc + (MODE == 0 ? z * 272 : (1 - z) * 272);
    const __nv_bfloat16* A2 = Xn + z * 408;
    const __nv_bfloat16* Bsrc = Wcat + (size_t)z * GATES * KCAT;

    wmma::fragment<wmma::accumulator, 16, 16, 16, float> acc[2][4];
    #pragma unroll
    for (int i = 0; i < 2; ++i)
        #pragma unroll
        for (int j = 0; j < 4; ++j)
            wmma::fill_fragment(acc[i][j], 0.0f);

    const int nS = (KACT + 63) >> 6;

    auto load_stage = [&](int s, int buf) {
        const int k0 = s * 64;
        #pragma unroll
        for (int it = 0; it < 4; ++it) {
            int c   = tid + it * 256;
            int row = c >> 3;
            int kc  = (c & 7) * 8;
            int kg  = k0 + kc;
            bool kv = kg < KACT;
            const __nv_bfloat16* ap;
            if (MODE == 0 || kg < 272)
                ap = A1 + (size_t)(bm0 + row) * 544 + (kv ? kg : 0);
            else
                ap = A2 + (size_t)(bm0 + row) * 544 + (kv ? (kg - 272) : 0);
            cp16(smA + buf * STG + row * 144 + kc * 2, ap, kv ? 16 : 0);
            int n   = bn0 + row;
            bool bok = kv && (n < GATES);
            const __nv_bfloat16* bp = Bsrc + (size_t)(n < GATES ? n : 0) * KCAT
                                           + (kv ? kg : 0);
            cp16(smB + buf * STG + row * 144 + kc * 2, bp, bok ? 16 : 0);
        }
        asm volatile("cp.async.commit_group;\n");
    };

    load_stage(0, 0);
    if (nS > 1) load_stage(1, 1);

    for (int s = 0; s < nS; ++s) {
        if (s + 2 < nS) load_stage(s + 2, (s + 2) % 3);
        cp_wait_n(nS - 1 - s < 2 ? nS - 1 - s : 2);
        __syncthreads();

        const int buf = s % 3;
        const __nv_bfloat16* Ab = reinterpret_cast<const __nv_bfloat16*>(dsm) + buf * (128 * 72);
        const __nv_bfloat16* Bb = reinterpret_cast<const __nv_bfloat16*>(dsm + 3 * STG) + buf * (128 * 72);

        #pragma unroll
        for (int ks = 0; ks < 4; ++ks) {
            const int kk = ks * 16;
            wmma::fragment<wmma::matrix_a, 16, 16, 16, __nv_bfloat16, wmma::row_major> af[2];
            wmma::fragment<wmma::matrix_b, 16, 16, 16, __nv_bfloat16, wmma::col_major> bfr[4];
            #pragma unroll
            for (int i = 0; i < 2; ++i)
                wmma::load_matrix_sync(af[i], Ab + (wm0 + i * 16) * 72 + kk, 72);
            #pragma unroll
            for (int j = 0; j < 4; ++j)
                wmma::load_matrix_sync(bfr[j], Bb + (wn0 + j * 16) * 72 + kk, 72);
            #pragma unroll
            for (int i = 0; i < 2; ++i)
                #pragma unroll
                for (int j = 0; j < 4; ++j)
                    wmma::mma_sync(acc[i][j], af[i], bfr[j], acc[i][j]);
        }
        __syncthreads();
    }

    // ---- fused LSTM epilogue (MUFU tanh) ------------------------------------
    float* stageW = reinterpret_cast<float*>(dsm) + warpI * 320;
    const int rr = lane >> 1;
    const int cc = (lane & 1) * 8;

    const float* bs = bsum + z * 544;
    float* Csel = z ? Cb : Cf;
    const int hoff = (MODE == 0) ? (z ? 408 : 0) : (z ? 136 : 272);

    #pragma unroll
    for (int i = 0; i < 2; ++i) {
        #pragma unroll
        for (int j = 0; j < 4; ++j) {
            const int cg0 = bn0 + wn0 + j * 16;
            if (cg0 >= GATES) continue;
            wmma::store_matrix_sync(stageW, acc[i][j], 20, wmma::mem_row_major);
            __syncwarp();

            const int b  = bm0 + wm0 + i * 16 + rr;
            const int gc = cg0 + cc;
            float4 v0 = *reinterpret_cast<float4*>(&stageW[rr * 20 + cc]);
            float4 v1 = *reinterpret_cast<float4*>(&stageW[rr * 20 + cc + 4]);
            __syncwarp();

            const float4 b0 = *reinterpret_cast<const float4*>(bs + gc);
            const float4 b1 = *reinterpret_cast<const float4*>(bs + gc + 4);

            #pragma unroll
            for (int q = 0; q < 2; ++q) {
                float4 v  = q ? v1 : v0;
                float4 bb = q ? b1 : b0;
                int j2 = ((gc + q * 4) >> 2);
                float gi = v.x + bb.x;
                float gf = v.y + bb.y;
                float gg = v.z + bb.z;
                float go = v.w + bb.w;
                float c;
                if (MODE == 0) c = fast_sigm(gi) * fast_tanh(gg);
                else           c = fast_sigm(gf) * Csel[(size_t)b * HH + j2]
                                 + fast_sigm(gi) * fast_tanh(gg);
                float h = fast_sigm(go) * fast_tanh(c);
                if (MODE == 0) Csel[(size_t)b * HH + j2] = c;
                Xn[(size_t)b * 544 + hoff + j2] = __float2bfloat16(h);
            }
        }
    }
}

// ---------------- fused head: cooperative, vectorized u_hat -----------------
#define EPB 4
__global__ __launch_bounds__(128 * EPB)
void head_kernel(const __nv_bfloat16* __restrict__ X,
                 const float* __restrict__ conv_w,
                 const float* __restrict__ conv_b,
                 const __nv_bfloat16* __restrict__ Wcb,
                 const float* __restrict__ fc1_w,
                 const float* __restrict__ fc1_b,
                 const float* __restrict__ fc2_w,
                 const float* __restrict__ fc2_b,
                 float* __restrict__ out, int out_size)
{
    extern __shared__ float hsm[];
    float* xs_a    = hsm;
    float* u_a     = xs_a + EPB * 2 * LL;
    float* sred_a  = u_a + EPB * NCAPS * LL;
    float* scale_a = sred_a + EPB * NCAPS * 4;
    float* uhat_a  = scale_a + EPB * NCAPS;
    float* vv_a    = uhat_a + EPB * NCAPS * OUTC;
    float* wred_a  = vv_a + EPB * OUTC;

    const int tid  = threadIdx.x;
    const int e    = tid >> 7;
    const int t    = tid & 127;
    const int lane = tid & 31;
    const int W16  = tid >> 5;
    const int w4   = W16 & 3;
    const int b    = blockIdx.x * EPB + e;
    const __nv_bfloat16* x = X + (size_t)b * 544;

    float* xs    = xs_a    + e * 2 * LL;
    float* u     = u_a     + e * NCAPS * LL;
    float* scale = scale_a + e * NCAPS;
    float* vv    = vv_a    + e * OUTC;
    float* wred  = wred_a  + e * 8;

    for (int i = t; i < 544; i += 128)
        xs[i] = __bfloat162float(x[i]);
    __syncthreads();

    for (int idx = t; idx < NCAPS * LL; idx += 128) {
        int c = idx / LL, k = idx % LL;
        int dd = (c >> 1) + 1, o = c & 1;
        int left = dd >> 1;
        const float* w = conv_w + (size_t)((dd - 1) * 2 + o) * 4;
        float acc = conv_b[(dd - 1) * 2 + o];
        #pragma unroll
        for (int i = 0; i < 2; ++i)
            #pragma unroll
            for (int kk = 0; kk < 2; ++kk) {
                int p = k + kk * dd - left;
                if (p >= 0 && p < LL) acc += w[i * 2 + kk] * xs[i * LL + p];
            }
        u[c * LL + k] = acc;
    }
    __syncthreads();

    #pragma unroll
    for (int c = 0; c < NCAPS; ++c) {
        float q0 = u[c * LL + t];
        float q1 = u[c * LL + t + 128];
        float p  = q0 * q0 + q1 * q1;
        if (t < 16) { float q2 = u[c * LL + t + 256]; p += q2 * q2; }
        #pragma unroll
        for (int off = 16; off > 0; off >>= 1)
            p += __shfl_down_sync(0xffffffffu, p, off);
        if (lane == 0) sred_a[(e * NCAPS + c) * 4 + w4] = p;
    }
    __syncthreads();
    if (t < NCAPS) {
        const float* sr = &sred_a[(e * NCAPS + t) * 4];
        float s2 = sr[0] + sr[1] + sr[2] + sr[3];
        float n = sqrtf(s2);
        scale[t] = (1.f - 1.f / (expf(n) + 1e-20f)) / (n + 1e-20f);
    }
    __syncthreads();

    // ---- u_hat: vectorized (bf16x2 W loads, float2 smem reads) ----
    for (int p = W16; p < NCAPS * OUTC; p += 16) {
        int c = p >> 4;
        const __nv_bfloat162* wr2 =
            reinterpret_cast<const __nv_bfloat162*>(Wcb + (size_t)p * LL);
        const float2* u0 = reinterpret_cast<const float2*>(u_a + 0 * NCAPS * LL + c * LL);
        const float2* u1 = reinterpret_cast<const float2*>(u_a + 1 * NCAPS * LL + c * LL);
        const float2* u2 = reinterpret_cast<const float2*>(u_a + 2 * NCAPS * LL + c * LL);
        const float2* u3 = reinterpret_cast<const float2*>(u_a + 3 * NCAPS * LL + c * LL);
        float a0 = 0.f, a1 = 0.f, a2 = 0.f, a3 = 0.f;
        #pragma unroll
        for (int s = 0; s < 5; ++s) {
            int kp = s * 32 + lane;
            if (kp < LL / 2) {
                float2 w2 = __bfloat1622float2(wr2[kp]);
                float2 q;
                q = u0[kp]; a0 += w2.x * q.x + w2.y * q.y;
                q = u1[kp]; a1 += w2.x * q.x + w2.y * q.y;
                q = u2[kp]; a2 += w2.x * q.x + w2.y * q.y;
                q = u3[kp]; a3 += w2.x * q.x + w2.y * q.y;
            }
        }
        #pragma unroll
        for (int off = 16; off > 0; off >>= 1) {
            a0 += __shfl_down_sync(0xffffffffu, a0, off);
            a1 += __shfl_down_sync(0xffffffffu, a1, off);
            a2 += __shfl_down_sync(0xffffffffu, a2, off);
            a3 += __shfl_down_sync(0xffffffffu, a3, off);
        }
        if (lane == 0) {
            uhat_a[0 * 160 + p] = a0 * scale_a[0 * NCAPS + c];
            uhat_a[1 * 160 + p] = a1 * scale_a[1 * NCAPS + c];
            uhat_a[2 * 160 + p] = a2 * scale_a[2 * NCAPS + c];
            uhat_a[3 * 160 + p] = a3 * scale_a[3 * NCAPS + c];
        }
    }
    __syncthreads();

    if (t < OUTC) {
        float s = 0.f;
        #pragma unroll
        for (int c = 0; c < NCAPS; ++c) s += uhat_a[e * 160 + c * OUTC + t];
        float sq = s * s;
        #pragma unroll
        for (int off = 8; off > 0; off >>= 1)
            sq += __shfl_xor_sync(0x0000ffffu, sq, off);
        float f = sq / (1.f + sq) / sqrtf(sq);
        vv[t] = f * s;
    }
    __syncthreads();

    float p0 = 0.f, p1 = 0.f;
    for (int j = t; j < HH; j += 128) {
        float h = fc1_b[j];
        #pragma unroll
        for (int o = 0; o < OUTC; ++o) h += vv[o] * fc1_w[j * OUTC + o];
        h = fmaxf(h, 0.f);
        p0 += fc2_w[j] * h;
        p1 += fc2_w[HH + j] * h;
    }
    #pragma unroll
    for (int off = 16; off > 0; off >>= 1) {
        p0 += __shfl_down_sync(0xffffffffu, p0, off);
        p1 += __shfl_down_sync(0xffffffffu, p1, off);
    }
    if (lane == 0) { wred[w4 * 2 + 0] = p0; wred[w4 * 2 + 1] = p1; }
    __syncthreads();

    if (t == 0) {
        float l0 = fc2_b[0], l1 = fc2_b[1];
        #pragma unroll
        for (int ww = 0; ww < 4; ++ww) { l0 += wred[ww * 2 + 0]; l1 += wred[ww * 2 + 1]; }
        out[(size_t)b * 2 + 0] = l0;
        out[(size_t)b * 2 + 1] = l1;
        if (out_size >= 4 * BATCH) {
            float m = fmaxf(l0, l1);
            float e0 = expf(l0 - m), e1 = expf(l1 - m);
            float den = e0 + e1;
            out[(size_t)2 * BATCH + b * 2 + 0] = e0 / den;
            out[(size_t)2 * BATCH + b * 2 + 1] = e1 / den;
        }
    }
}

// ---------------- launch ----------------------------------------------------
extern "C" void kernel_launch(void* const* d_in, const int* in_sizes, int n_in,
                              void* d_out, int out_size)
{
    const int*   seq    = (const int*)  d_in[0];
    const float* sig    = (const float*)d_in[1];
    const float* embed  = (const float*)d_in[2];
    const float* w_ih   = (const float*)d_in[3];
    const float* w_hh   = (const float*)d_in[4];
    const float* b_ih   = (const float*)d_in[5];
    const float* b_hh   = (const float*)d_in[6];
    const float* conv_w = (const float*)d_in[7];
    const float* conv_b = (const float*)d_in[8];
    const float* W_caps = (const float*)d_in[9];
    const float* fc1_w  = (const float*)d_in[10];
    const float* fc1_b  = (const float*)d_in[11];
    const float* fc2_w  = (const float*)d_in[12];
    const float* fc2_b  = (const float*)d_in[13];
    float* out = (float*)d_out;

    __nv_bfloat16 *X0, *X1, *Wcat, *Wcb;
    float *Cf, *Cb, *Bsum;
    cudaGetSymbolAddress((void**)&X0,   g_Xb0);
    cudaGetSymbolAddress((void**)&X1,   g_Xb1);
    cudaGetSymbolAddress((void**)&Cf,   g_Cf);
    cudaGetSymbolAddress((void**)&Cb,   g_Cb);
    cudaGetSymbolAddress((void**)&Wcat, g_Wcat);
    cudaGetSymbolAddress((void**)&Bsum, g_Bs);
    cudaGetSymbolAddress((void**)&Wcb,  g_Wcb);
    __nv_bfloat16* Xs[2] = {X0, X1};

    const int SMEM_G = 3 * 128 * 72 * 2 * 2;     // 110592
    const int SMEM_H = (EPB * (2*LL + NCAPS*LL + NCAPS*4 + NCAPS + NCAPS*OUTC + OUTC + 8)) * 4;
    cudaFuncSetAttribute(gemm_lstm<272, 0>,
                         cudaFuncAttributeMaxDynamicSharedMemorySize, SMEM_G);
    cudaFuncSetAttribute(gemm_lstm<408, 1>,
                         cudaFuncAttributeMaxDynamicSharedMemorySize, SMEM_G);
    cudaFuncSetAttribute(head_kernel,
                         cudaFuncAttributeMaxDynamicSharedMemorySize, SMEM_H);

    prep_kernel<<<(BATCH * LL + 255) / 256, 256>>>(seq, sig, embed, X0);

    const int nWtot = NL * 2 * GATES * KCAT + NL * GCOLS + NCAPS * OUTC * LL;
    weights_kernel<<<(nWtot + 255) / 256, 256>>>(w_ih, w_hh, b_ih, b_hh, W_caps,
                                                 Wcat, Bsum, Wcb);

    dim3 grid(5, BATCH / 128, 2);
    for (int l = 0; l < NL; ++l) {
        __nv_bfloat16* Xc = Xs[l & 1];
        __nv_bfloat16* Xn = Xs[(l + 1) & 1];
        const __nv_bfloat16* Wl = Wcat + (size_t)l * 2 * GATES * KCAT;
        const float* Bl = Bsum + (size_t)l * GCOLS;

        gemm_lstm<272, 0><<<grid, 256, SMEM_G>>>(Xc, Wl, Bl, Xn, Cf, Cb);
        gemm_lstm<408, 1><<<grid, 256, SMEM_G>>>(Xc, Wl, Bl, Xn, Cf, Cb);
    }

    head_kernel<<<BATCH / EPB, 128 * EPB, SMEM_H>>>(X1, conv_w, conv_b, Wcb,
                                                    fc1_w, fc1_b, fc2_w, fc2_b,
                                                    out, out_size);
}

// round 14
// speedup vs baseline: 1.1214x; 1.0111x over previous
#include <cuda_runtime.h>
#include <cuda_bf16.h>
#include <mma.h>
#include <cstdint>

using namespace nvcuda;

// ---------------- problem constants ----------------
#define BATCH   16384
#define KMER    17
#define HH      136
#define LL      272
#define GATES   544
#define GCOLS   1088
#define NL      3
#define OUTC    16
#define NCAPS   10
#define KCAT    408           // 272 + 136 concatenated K

// ---------------- device scratch --------------------------------------------
__device__ __align__(256) __nv_bfloat16 g_Xb0[(size_t)BATCH * 2 * LL];
__device__ __align__(256) __nv_bfloat16 g_Xb1[(size_t)BATCH * 2 * LL];
__device__ __align__(256) float         g_Cf [(size_t)BATCH * HH];
__device__ __align__(256) float         g_Cb [(size_t)BATCH * HH];
__device__ __align__(256) __nv_bfloat16 g_Wcat[(size_t)NL * 2 * GATES * KCAT];
__device__ __align__(256) float         g_Bs [(size_t)NL * GCOLS];
__device__ __align__(256) __nv_bfloat16 g_Wcb[(size_t)NCAPS * OUTC * LL];

// ---------------- fast transcendentals (MUFU tanh, sm_75+) -------------------
__device__ __forceinline__ float fast_tanh(float x) {
    float r;
    asm("tanh.approx.f32 %0, %1;" : "=f"(r) : "f"(x));
    return r;
}
__device__ __forceinline__ float fast_sigm(float x) {
    return fmaf(fast_tanh(0.5f * x), 0.5f, 0.5f);
}

__device__ __forceinline__ uint32_t smem_u32(const void* p) {
    uint32_t a;
    asm("{ .reg .u64 t; cvta.to.shared.u64 t, %1; cvt.u32.u64 %0, t; }" : "=r"(a) : "l"(p));
    return a;
}
__device__ __forceinline__ void cp16(uint32_t smaddr, const void* g, int sb) {
    asm volatile("cp.async.cg.shared.global [%0], [%1], 16, %2;\n"
                 :: "r"(smaddr), "l"(g), "r"(sb));
}
__device__ __forceinline__ void cp_wait_n(int n) {
    if (n <= 0)      asm volatile("cp.async.wait_group 0;");
    else             asm volatile("cp.async.wait_group 1;");
}

// ---------------- setup: prep input + all weight conversions (1 launch) -----
__global__ void setup_kernel(const int* __restrict__ seq,
                             const float* __restrict__ sig,
                             const float* __restrict__ embed,
                             const float* __restrict__ wih,
                             const float* __restrict__ whh,
                             const float* __restrict__ bih,
                             const float* __restrict__ bhh,
                             const float* __restrict__ wcaps,
                             __nv_bfloat16* __restrict__ X,
                             __nv_bfloat16* __restrict__ wcat,
                             float* __restrict__ bsum,
                             __nv_bfloat16* __restrict__ wcb)
{
    const long long nPrep = (long long)BATCH * LL;                 // 4456448
    const long long nW    = (long long)NL * 2 * GATES * KCAT;      // 1331712
    const long long nB    = NL * GCOLS;                            // 3264
    const long long nC    = NCAPS * OUTC * LL;                     // 43520
    long long i = (long long)blockIdx.x * blockDim.x + threadIdx.x;

    if (i < nPrep) {
        int b = (int)(i / LL), r = (int)(i % LL);
        int p = r >> 4, e = r & 15;
        int tok = seq[b * KMER + p];
        X[(size_t)b * 544 + r]       = __float2bfloat16(embed[tok * 16 + e]);
        X[(size_t)b * 544 + 272 + r] = __float2bfloat16(sig[(size_t)b * LL + r]);
        return;
    }
    i -= nPrep;
    if (i < nW) {
        const int per = GATES * KCAT;
        int ld = (int)(i / per);  int r = (int)(i % per);
        int n = r / KCAT, k = r % KCAT;
        int j = n >> 2, g = n & 3;
        float v = (k < 272)
            ? wih[((size_t)ld * GATES + g * HH + j) * LL + k]
            : whh[((size_t)ld * GATES + g * HH + j) * HH + (k - 272)];
        wcat[i] = __float2bfloat16(v);
        return;
    }
    i -= nW;
    if (i < nB) {
        int l = (int)(i / GCOLS); int np = (int)(i % GCOLS);
        int d = np / GATES, q = np % GATES;
        int j = q >> 2, g = q & 3;
        int src = (l * 2 + d) * GATES + g * HH + j;
        bsum[i] = bih[src] + bhh[src];
        return;
    }
    i -= nB;
    if (i < nC) wcb[i] = __float2bfloat16(wcaps[i]);
}

// ---------------- compute KS k-steps of one 64-K stage (fully unrolled) ------
template<int KS>
__device__ __forceinline__ void mma_ks(const __nv_bfloat16* __restrict__ Ab,
                                       const __nv_bfloat16* __restrict__ Bb,
                                       int wm0, int wn0,
                                       wmma::fragment<wmma::accumulator, 16, 16, 16, float> (&acc)[2][4])
{
    #pragma unroll
    for (int ks = 0; ks < KS; ++ks) {
        const int kk = ks * 16;
        wmma::fragment<wmma::matrix_a, 16, 16, 16, __nv_bfloat16, wmma::row_major> af[2];
        wmma::fragment<wmma::matrix_b, 16, 16, 16, __nv_bfloat16, wmma::col_major> bfr[4];
        #pragma unroll
        for (int i = 0; i < 2; ++i)
            wmma::load_matrix_sync(af[i], Ab + (wm0 + i * 16) * 72 + kk, 72);
        #pragma unroll
        for (int j = 0; j < 4; ++j)
            wmma::load_matrix_sync(bfr[j], Bb + (wn0 + j * 16) * 72 + kk, 72);
        #pragma unroll
        for (int i = 0; i < 2; ++i)
            #pragma unroll
            for (int j = 0; j < 4; ++j)
                wmma::mma_sync(acc[i][j], af[i], bfr[j], acc[i][j]);
    }
}

// ---------------- fused LSTM GEMM (wmma bf16, NT, 3-stage ring, 1 barrier) ---
// Block tile 128x128, BK=64, 8 warps (32x64 each). z = blockIdx.z = direction.
// MODE 0: gates_first = x_first @ Wih^T + b ; cell1 (c_prev=0) -> h, C.
// MODE 1: gates_second = [x_second | h_first] @ Wcat^T + b ; cell2 -> h.
template<int KACT, int MODE>
__global__ __launch_bounds__(256, 2)
void gemm_lstm(const __nv_bfloat16* __restrict__ Xc,
               const __nv_bfloat16* __restrict__ Wcat,
               const float* __restrict__ bsum,
               __nv_bfloat16* __restrict__ Xn,
               float* __restrict__ Cf, float* __restrict__ Cb)
{
    extern __shared__ __align__(16) char dsm[];
    const int STG = 128 * 72 * 2;          // 18432 B per stage per matrix

    const int tid   = threadIdx.x;
    const int warpI = tid >> 5;
    const int lane  = tid & 31;
    const int z     = blockIdx.z;
    const int bm0   = blockIdx.y * 128;
    const int bn0   = blockIdx.x * 128;
    const int wm0   = (warpI & 3) * 32;
    const int wn0   = (warpI >> 2) * 64;

    const uint32_t smA = smem_u32(dsm);
    const uint32_t smB = smA + 3 * STG;

    const __nv_bfloat16* A1 = Xc + (MODE == 0 ? z * 272 : (1 - z) * 272);
    const __nv_bfloat16* A2 = Xn + z * 408;
    const __nv_bfloat16* Bsrc = Wcat + (size_t)z * GATES * KCAT;

    wmma::fragment<wmma::accumulator, 16, 16, 16, float> acc[2][4];
    #pragma unroll
    for (int i = 0; i < 2; ++i)
        #pragma unroll
        for (int j = 0; j < 4; ++j)
            wmma::fill_fragment(acc[i][j], 0.0f);

    constexpr int nS      = (KACT + 63) >> 6;                 // 5 or 7
    constexpr int KS_LAST = (KACT - (nS - 1) * 64 + 15) >> 4; // 1 or 2

    auto load_stage = [&](int s, int buf) {
        const int k0 = s * 64;
        #pragma unroll
        for (int it = 0; it < 4; ++it) {
            int c   = tid + it * 256;
            int row = c >> 3;
            int kc  = (c & 7) * 8;
            int kg  = k0 + kc;
            bool kv = kg < KACT;
            const __nv_bfloat16* ap;
            if (MODE == 0 || kg < 272)
                ap = A1 + (size_t)(bm0 + row) * 544 + (kv ? kg : 0);
            else
                ap = A2 + (size_t)(bm0 + row) * 544 + (kv ? (kg - 272) : 0);
            cp16(smA + buf * STG + row * 144 + kc * 2, ap, kv ? 16 : 0);
            int n   = bn0 + row;
            bool bok = kv && (n < GATES);
            const __nv_bfloat16* bp = Bsrc + (size_t)(n < GATES ? n : 0) * KCAT
                                           + (kv ? kg : 0);
            cp16(smB + buf * STG + row * 144 + kc * 2, bp, bok ? 16 : 0);
        }
        asm volatile("cp.async.commit_group;\n");
    };

    load_stage(0, 0);
    load_stage(1, 1);

    // full stages 0..nS-2 : wait -> barrier -> prefetch s+2 -> compute<4>
    #pragma unroll 1
    for (int s = 0; s < nS - 1; ++s) {
        cp_wait_n(1);
        __syncthreads();
        if (s + 2 < nS) load_stage(s + 2, (s + 2) % 3);
        const int buf = s % 3;
        mma_ks<4>(reinterpret_cast<const __nv_bfloat16*>(dsm) + buf * (128 * 72),
                  reinterpret_cast<const __nv_bfloat16*>(dsm + 3 * STG) + buf * (128 * 72),
                  wm0, wn0, acc);
    }
    // last stage: compile-time trimmed k-steps
    {
        cp_wait_n(0);
        __syncthreads();
        const int buf = (nS - 1) % 3;
        mma_ks<KS_LAST>(reinterpret_cast<const __nv_bfloat16*>(dsm) + buf * (128 * 72),
                        reinterpret_cast<const __nv_bfloat16*>(dsm + 3 * STG) + buf * (128 * 72),
                        wm0, wn0, acc);
    }
    __syncthreads();    // protect smem reuse by epilogue staging

    // ---- fused LSTM epilogue (MUFU tanh) ------------------------------------
    float* stageW = reinterpret_cast<float*>(dsm) + warpI * 320;
    const int rr = lane >> 1;
    const int cc = (lane & 1) * 8;

    const float* bs = bsum + z * 544;
    float* Csel = z ? Cb : Cf;
    const int hoff = (MODE == 0) ? (z ? 408 : 0) : (z ? 136 : 272);

    #pragma unroll
    for (int i = 0; i < 2; ++i) {
        #pragma unroll
        for (int j = 0; j < 4; ++j) {
            const int cg0 = bn0 + wn0 + j * 16;
            if (cg0 >= GATES) continue;
            wmma::store_matrix_sync(stageW, acc[i][j], 20, wmma::mem_row_major);
            __syncwarp();

            const int b  = bm0 + wm0 + i * 16 + rr;
            const int gc = cg0 + cc;
            float4 v0 = *reinterpret_cast<float4*>(&stageW[rr * 20 + cc]);
            float4 v1 = *reinterpret_cast<float4*>(&stageW[rr * 20 + cc + 4]);
            __syncwarp();

            const float4 b0 = *reinterpret_cast<const float4*>(bs + gc);
            const float4 b1 = *reinterpret_cast<const float4*>(bs + gc + 4);

            #pragma unroll
            for (int q = 0; q < 2; ++q) {
                float4 v  = q ? v1 : v0;
                float4 bb = q ? b1 : b0;
                int j2 = ((gc + q * 4) >> 2);
                float gi = v.x + bb.x;
                float gf = v.y + bb.y;
                float gg = v.z + bb.z;
                float go = v.w + bb.w;
                float c;
                if (MODE == 0) c = fast_sigm(gi) * fast_tanh(gg);
                else           c = fast_sigm(gf) * Csel[(size_t)b * HH + j2]
                                 + fast_sigm(gi) * fast_tanh(gg);
                float h = fast_sigm(go) * fast_tanh(c);
                if (MODE == 0) Csel[(size_t)b * HH + j2] = c;
                Xn[(size_t)b * 544 + hoff + j2] = __float2bfloat16(h);
            }
        }
    }
}

// ---------------- fused head: cooperative, vectorized u_hat -----------------
#define EPB 4
__global__ __launch_bounds__(128 * EPB)
void head_kernel(const __nv_bfloat16* __restrict__ X,
                 const float* __restrict__ conv_w,
                 const float* __restrict__ conv_b,
                 const __nv_bfloat16* __restrict__ Wcb,
                 const float* __restrict__ fc1_w,
                 const float* __restrict__ fc1_b,
                 const float* __restrict__ fc2_w,
                 const float* __restrict__ fc2_b,
                 float* __restrict__ out, int out_size)
{
    extern __shared__ float hsm[];
    float* xs_a    = hsm;
    float* u_a     = xs_a + EPB * 2 * LL;
    float* sred_a  = u_a + EPB * NCAPS * LL;
    float* scale_a = sred_a + EPB * NCAPS * 4;
    float* uhat_a  = scale_a + EPB * NCAPS;
    float* vv_a    = uhat_a + EPB * NCAPS * OUTC;
    float* wred_a  = vv_a + EPB * OUTC;

    const int tid  = threadIdx.x;
    const int e    = tid >> 7;
    const int t    = tid & 127;
    const int lane = tid & 31;
    const int W16  = tid >> 5;
    const int w4   = W16 & 3;
    const int b    = blockIdx.x * EPB + e;
    const __nv_bfloat16* x = X + (size_t)b * 544;

    float* xs    = xs_a    + e * 2 * LL;
    float* u     = u_a     + e * NCAPS * LL;
    float* scale = scale_a + e * NCAPS;
    float* vv    = vv_a    + e * OUTC;
    float* wred  = wred_a  + e * 8;

    for (int i = t; i < 544; i += 128)
        xs[i] = __bfloat162float(x[i]);
    __syncthreads();

    for (int idx = t; idx < NCAPS * LL; idx += 128) {
        int c = idx / LL, k = idx % LL;
        int dd = (c >> 1) + 1, o = c & 1;
        int left = dd >> 1;
        const float* w = conv_w + (size_t)((dd - 1) * 2 + o) * 4;
        float acc = conv_b[(dd - 1) * 2 + o];
        #pragma unroll
        for (int i = 0; i < 2; ++i)
            #pragma unroll
            for (int kk = 0; kk < 2; ++kk) {
                int p = k + kk * dd - left;
                if (p >= 0 && p < LL) acc += w[i * 2 + kk] * xs[i * LL + p];
            }
        u[c * LL + k] = acc;
    }
    __syncthreads();

    #pragma unroll
    for (int c = 0; c < NCAPS; ++c) {
        float q0 = u[c * LL + t];
        float q1 = u[c * LL + t + 128];
        float p  = q0 * q0 + q1 * q1;
        if (t < 16) { float q2 = u[c * LL + t + 256]; p += q2 * q2; }
        #pragma unroll
        for (int off = 16; off > 0; off >>= 1)
            p += __shfl_down_sync(0xffffffffu, p, off);
        if (lane == 0) sred_a[(e * NCAPS + c) * 4 + w4] = p;
    }
    __syncthreads();
    if (t < NCAPS) {
        const float* sr = &sred_a[(e * NCAPS + t) * 4];
        float s2 = sr[0] + sr[1] + sr[2] + sr[3];
        float n = sqrtf(s2);
        scale[t] = (1.f - 1.f / (expf(n) + 1e-20f)) / (n + 1e-20f);
    }
    __syncthreads();

    for (int p = W16; p < NCAPS * OUTC; p += 16) {
        int c = p >> 4;
        const __nv_bfloat162* wr2 =
            reinterpret_cast<const __nv_bfloat162*>(Wcb + (size_t)p * LL);
        const float2* u0 = reinterpret_cast<const float2*>(u_a + 0 * NCAPS * LL + c * LL);
        const float2* u1 = reinterpret_cast<const float2*>(u_a + 1 * NCAPS * LL + c * LL);
        const float2* u2 = reinterpret_cast<const float2*>(u_a + 2 * NCAPS * LL + c * LL);
        const float2* u3 = reinterpret_cast<const float2*>(u_a + 3 * NCAPS * LL + c * LL);
        float a0 = 0.f, a1 = 0.f, a2 = 0.f, a3 = 0.f;
        #pragma unroll
        for (int s = 0; s < 5; ++s) {
            int kp = s * 32 + lane;
            if (kp < LL / 2) {
                float2 w2 = __bfloat1622float2(wr2[kp]);
                float2 q;
                q = u0[kp]; a0 += w2.x * q.x + w2.y * q.y;
                q = u1[kp]; a1 += w2.x * q.x + w2.y * q.y;
                q = u2[kp]; a2 += w2.x * q.x + w2.y * q.y;
                q = u3[kp]; a3 += w2.x * q.x + w2.y * q.y;
            }
        }
        #pragma unroll
        for (int off = 16; off > 0; off >>= 1) {
            a0 += __shfl_down_sync(0xffffffffu, a0, off);
            a1 += __shfl_down_sync(0xffffffffu, a1, off);
            a2 += __shfl_down_sync(0xffffffffu, a2, off);
            a3 += __shfl_down_sync(0xffffffffu, a3, off);
        }
        if (lane == 0) {
            uhat_a[0 * 160 + p] = a0 * scale_a[0 * NCAPS + c];
            uhat_a[1 * 160 + p] = a1 * scale_a[1 * NCAPS + c];
            uhat_a[2 * 160 + p] = a2 * scale_a[2 * NCAPS + c];
            uhat_a[3 * 160 + p] = a3 * scale_a[3 * NCAPS + c];
        }
    }
    __syncthreads();

    if (t < OUTC) {
        float s = 0.f;
        #pragma unroll
        for (int c = 0; c < NCAPS; ++c) s += uhat_a[e * 160 + c * OUTC + t];
        float sq = s * s;
        #pragma unroll
        for (int off = 8; off > 0; off >>= 1)
            sq += __shfl_xor_sync(0x0000ffffu, sq, off);
        float f = sq / (1.f + sq) / sqrtf(sq);
        vv[t] = f * s;
    }
    __syncthreads();

    float p0 = 0.f, p1 = 0.f;
    for (int j = t; j < HH; j += 128) {
        float h = fc1_b[j];
        #pragma unroll
        for (int o = 0; o < OUTC; ++o) h += vv[o] * fc1_w[j * OUTC + o];
        h = fmaxf(h, 0.f);
        p0 += fc2_w[j] * h;
        p1 += fc2_w[HH + j] * h;
    }
    #pragma unroll
    for (int off = 16; off > 0; off >>= 1) {
        p0 += __shfl_down_sync(0xffffffffu, p0, off);
        p1 += __shfl_down_sync(0xffffffffu, p1, off);
    }
    if (lane == 0) { wred[w4 * 2 + 0] = p0; wred[w4 * 2 + 1] = p1; }
    __syncthreads();

    if (t == 0) {
        float l0 = fc2_b[0], l1 = fc2_b[1];
        #pragma unroll
        for (int ww = 0; ww < 4; ++ww) { l0 += wred[ww * 2 + 0]; l1 += wred[ww * 2 + 1]; }
        out[(size_t)b * 2 + 0] = l0;
        out[(size_t)b * 2 + 1] = l1;
        if (out_size >= 4 * BATCH) {
            float m = fmaxf(l0, l1);
            float e0 = expf(l0 - m), e1 = expf(l1 - m);
            float den = e0 + e1;
            out[(size_t)2 * BATCH + b * 2 + 0] = e0 / den;
            out[(size_t)2 * BATCH + b * 2 + 1] = e1 / den;
        }
    }
}

// ---------------- launch ----------------------------------------------------
extern "C" void kernel_launch(void* const* d_in, const int* in_sizes, int n_in,
                              void* d_out, int out_size)
{
    const int*   seq    = (const int*)  d_in[0];
    const float* sig    = (const float*)d_in[1];
    const float* embed  = (const float*)d_in[2];
    const float* w_ih   = (const float*)d_in[3];
    const float* w_hh   = (const float*)d_in[4];
    const float* b_ih   = (const float*)d_in[5];
    const float* b_hh   = (const float*)d_in[6];
    const float* conv_w = (const float*)d_in[7];
    const float* conv_b = (const float*)d_in[8];
    const float* W_caps = (const float*)d_in[9];
    const float* fc1_w  = (const float*)d_in[10];
    const float* fc1_b  = (const float*)d_in[11];
    const float* fc2_w  = (const float*)d_in[12];
    const float* fc2_b  = (const float*)d_in[13];
    float* out = (float*)d_out;

    __nv_bfloat16 *X0, *X1, *Wcat, *Wcb;
    float *Cf, *Cb, *Bsum;
    cudaGetSymbolAddress((void**)&X0,   g_Xb0);
    cudaGetSymbolAddress((void**)&X1,   g_Xb1);
    cudaGetSymbolAddress((void**)&Cf,   g_Cf);
    cudaGetSymbolAddress((void**)&Cb,   g_Cb);
    cudaGetSymbolAddress((void**)&Wcat, g_Wcat);
    cudaGetSymbolAddress((void**)&Bsum, g_Bs);
    cudaGetSymbolAddress((void**)&Wcb,  g_Wcb);
    __nv_bfloat16* Xs[2] = {X0, X1};

    const int SMEM_G = 3 * 128 * 72 * 2 * 2;     // 110592
    const int SMEM_H = (EPB * (2*LL + NCAPS*LL + NCAPS*4 + NCAPS + NCAPS*OUTC + OUTC + 8)) * 4;
    cudaFuncSetAttribute(gemm_lstm<272, 0>,
                         cudaFuncAttributeMaxDynamicSharedMemorySize, SMEM_G);
    cudaFuncSetAttribute(gemm_lstm<408, 1>,
                         cudaFuncAttributeMaxDynamicSharedMemorySize, SMEM_G);
    cudaFuncSetAttribute(head_kernel,
                         cudaFuncAttributeMaxDynamicSharedMemorySize, SMEM_H);

    const long long nSetup = (long long)BATCH * LL + (long long)NL * 2 * GATES * KCAT
                           + NL * GCOLS + NCAPS * OUTC * LL;
    setup_kernel<<<(int)((nSetup + 255) / 256), 256>>>(
        seq, sig, embed, w_ih, w_hh, b_ih, b_hh, W_caps, X0, Wcat, Bsum, Wcb);

    dim3 grid(5, BATCH / 128, 2);
    for (int l = 0; l < NL; ++l) {
        __nv_bfloat16* Xc = Xs[l & 1];
        __nv_bfloat16* Xn = Xs[(l + 1) & 1];
        const __nv_bfloat16* Wl = Wcat + (size_t)l * 2 * GATES * KCAT;
        const float* Bl = Bsum + (size_t)l * GCOLS;

        gemm_lstm<272, 0><<<grid, 256, SMEM_G>>>(Xc, Wl, Bl, Xn, Cf, Cb);
        gemm_lstm<408, 1><<<grid, 256, SMEM_G>>>(Xc, Wl, Bl, Xn, Cf, Cb);
    }

    head_kernel<<<BATCH / EPB, 128 * EPB, SMEM_H>>>(X1, conv_w, conv_b, Wcb,
                                                    fc1_w, fc1_b, fc2_w, fc2_b,
                                                    out, out_size);
}

// round 15
// speedup vs baseline: 1.1403x; 1.0168x over previous
#include <cuda_runtime.h>
#include <cuda_bf16.h>
#include <mma.h>
#include <cstdint>

using namespace nvcuda;

// ---------------- problem constants ----------------
#define BATCH   16384
#define KMER    17
#define HH      136
#define LL      272
#define GATES   544
#define GCOLS   1088
#define NL      3
#define OUTC    16
#define NCAPS   10
#define KCAT    408           // 272 + 136 concatenated K

// ---------------- device scratch --------------------------------------------
__device__ __align__(256) __nv_bfloat16 g_Xb0[(size_t)BATCH * 2 * LL];
__device__ __align__(256) __nv_bfloat16 g_Xb1[(size_t)BATCH * 2 * LL];
__device__ __align__(256) float         g_Cf [(size_t)BATCH * HH];
__device__ __align__(256) float         g_Cb [(size_t)BATCH * HH];
__device__ __align__(256) __nv_bfloat16 g_Wcat[(size_t)NL * 2 * GATES * KCAT];
__device__ __align__(256) float         g_Bs [(size_t)NL * GCOLS];
__device__ __align__(256) __nv_bfloat16 g_Wcb[(size_t)NCAPS * OUTC * LL];

// ---------------- fast transcendentals (MUFU tanh, sm_75+) -------------------
__device__ __forceinline__ float fast_tanh(float x) {
    float r;
    asm("tanh.approx.f32 %0, %1;" : "=f"(r) : "f"(x));
    return r;
}
__device__ __forceinline__ float fast_sigm(float x) {
    return fmaf(fast_tanh(0.5f * x), 0.5f, 0.5f);
}

__device__ __forceinline__ uint32_t smem_u32(const void* p) {
    uint32_t a;
    asm("{ .reg .u64 t; cvta.to.shared.u64 t, %1; cvt.u32.u64 %0, t; }" : "=r"(a) : "l"(p));
    return a;
}
__device__ __forceinline__ void cp16(uint32_t smaddr, const void* g, int sb) {
    asm volatile("cp.async.cg.shared.global [%0], [%1], 16, %2;\n"
                 :: "r"(smaddr), "l"(g), "r"(sb));
}
__device__ __forceinline__ void cp_wait_n(int n) {
    if (n <= 0)      asm volatile("cp.async.wait_group 0;");
    else             asm volatile("cp.async.wait_group 1;");
}

// ---------------- setup: prep input + all weight conversions (1 launch) -----
__global__ void setup_kernel(const int* __restrict__ seq,
                             const float* __restrict__ sig,
                             const float* __restrict__ embed,
                             const float* __restrict__ wih,
                             const float* __restrict__ whh,
                             const float* __restrict__ bih,
                             const float* __restrict__ bhh,
                             const float* __restrict__ wcaps,
                             __nv_bfloat16* __restrict__ X,
                             __nv_bfloat16* __restrict__ wcat,
                             float* __restrict__ bsum,
                             __nv_bfloat16* __restrict__ wcb)
{
    const long long nPrep = (long long)BATCH * LL;
    const long long nW    = (long long)NL * 2 * GATES * KCAT;
    const long long nB    = NL * GCOLS;
    const long long nC    = NCAPS * OUTC * LL;
    long long i = (long long)blockIdx.x * blockDim.x + threadIdx.x;

    if (i < nPrep) {
        int b = (int)(i / LL), r = (int)(i % LL);
        int p = r >> 4, e = r & 15;
        int tok = seq[b * KMER + p];
        X[(size_t)b * 544 + r]       = __float2bfloat16(embed[tok * 16 + e]);
        X[(size_t)b * 544 + 272 + r] = __float2bfloat16(sig[(size_t)b * LL + r]);
        return;
    }
    i -= nPrep;
    if (i < nW) {
        const int per = GATES * KCAT;
        int ld = (int)(i / per);  int r = (int)(i % per);
        int n = r / KCAT, k = r % KCAT;
        int j = n >> 2, g = n & 3;
        float v = (k < 272)
            ? wih[((size_t)ld * GATES + g * HH + j) * LL + k]
            : whh[((size_t)ld * GATES + g * HH + j) * HH + (k - 272)];
        wcat[i] = __float2bfloat16(v);
        return;
    }
    i -= nW;
    if (i < nB) {
        int l = (int)(i / GCOLS); int np = (int)(i % GCOLS);
        int d = np / GATES, q = np % GATES;
        int j = q >> 2, g = q & 3;
        int src = (l * 2 + d) * GATES + g * HH + j;
        bsum[i] = bih[src] + bhh[src];
        return;
    }
    i -= nB;
    if (i < nC) wcb[i] = __float2bfloat16(wcaps[i]);
}

// ---------------- compute KS k-steps of one 64-K stage (64x64 warp tile) -----
template<int KS>
__device__ __forceinline__ void mma_ks(const __nv_bfloat16* __restrict__ Ab,
                                       const __nv_bfloat16* __restrict__ Bb,
                                       int wm0, int wn0,
                                       wmma::fragment<wmma::accumulator, 16, 16, 16, float> (&acc)[4][4])
{
    #pragma unroll
    for (int ks = 0; ks < KS; ++ks) {
        const int kk = ks * 16;
        wmma::fragment<wmma::matrix_a, 16, 16, 16, __nv_bfloat16, wmma::row_major> af[4];
        wmma::fragment<wmma::matrix_b, 16, 16, 16, __nv_bfloat16, wmma::col_major> bfr[4];
        #pragma unroll
        for (int i = 0; i < 4; ++i)
            wmma::load_matrix_sync(af[i], Ab + (wm0 + i * 16) * 72 + kk, 72);
        #pragma unroll
        for (int j = 0; j < 4; ++j)
            wmma::load_matrix_sync(bfr[j], Bb + (wn0 + j * 16) * 72 + kk, 72);
        #pragma unroll
        for (int i = 0; i < 4; ++i)
            #pragma unroll
            for (int j = 0; j < 4; ++j)
                wmma::mma_sync(acc[i][j], af[i], bfr[j], acc[i][j]);
    }
}

// ---------------- fused LSTM GEMM (wmma bf16, NT, 3-stage ring) --------------
// Block tile 128x128, BK=64, 4 warps (64x64 each), 128 threads.
// z = blockIdx.z = direction.
// MODE 0: gates_first = x_first @ Wih^T + b ; cell1 (c_prev=0) -> h, C.
// MODE 1: gates_second = [x_second | h_first] @ Wcat^T + b ; cell2 -> h.
template<int KACT, int MODE>
__global__ __launch_bounds__(128, 2)
void gemm_lstm(const __nv_bfloat16* __restrict__ Xc,
               const __nv_bfloat16* __restrict__ Wcat,
               const float* __restrict__ bsum,
               __nv_bfloat16* __restrict__ Xn,
               float* __restrict__ Cf, float* __restrict__ Cb)
{
    extern __shared__ __align__(16) char dsm[];
    const int STG = 128 * 72 * 2;          // 18432 B per stage per matrix

    const int tid   = threadIdx.x;
    const int warpI = tid >> 5;            // 0..3
    const int lane  = tid & 31;
    const int z     = blockIdx.z;
    const int bm0   = blockIdx.y * 128;
    const int bn0   = blockIdx.x * 128;
    const int wm0   = (warpI & 1) * 64;    // 2 warps along M
    const int wn0   = (warpI >> 1) * 64;   // 2 warps along N

    const uint32_t smA = smem_u32(dsm);
    const uint32_t smB = smA + 3 * STG;

    const __nv_bfloat16* A1 = Xc + (MODE == 0 ? z * 272 : (1 - z) * 272);
    const __nv_bfloat16* A2 = Xn + z * 408;
    const __nv_bfloat16* Bsrc = Wcat + (size_t)z * GATES * KCAT;

    wmma::fragment<wmma::accumulator, 16, 16, 16, float> acc[4][4];
    #pragma unroll
    for (int i = 0; i < 4; ++i)
        #pragma unroll
        for (int j = 0; j < 4; ++j)
            wmma::fill_fragment(acc[i][j], 0.0f);

    constexpr int nS      = (KACT + 63) >> 6;                 // 5 or 7
    constexpr int KS_LAST = (KACT - (nS - 1) * 64 + 15) >> 4; // 1 or 2

    auto load_stage = [&](int s, int buf) {
        const int k0 = s * 64;
        #pragma unroll
        for (int it = 0; it < 8; ++it) {
            int c   = tid + it * 128;           // 0..1023
            int row = c >> 3;
            int kc  = (c & 7) * 8;
            int kg  = k0 + kc;
            bool kv = kg < KACT;
            const __nv_bfloat16* ap;
            if (MODE == 0 || kg < 272)
                ap = A1 + (size_t)(bm0 + row) * 544 + (kv ? kg : 0);
            else
                ap = A2 + (size_t)(bm0 + row) * 544 + (kv ? (kg - 272) : 0);
            cp16(smA + buf * STG + row * 144 + kc * 2, ap, kv ? 16 : 0);
            int n   = bn0 + row;
            bool bok = kv && (n < GATES);
            const __nv_bfloat16* bp = Bsrc + (size_t)(n < GATES ? n : 0) * KCAT
                                           + (kv ? kg : 0);
            cp16(smB + buf * STG + row * 144 + kc * 2, bp, bok ? 16 : 0);
        }
        asm volatile("cp.async.commit_group;\n");
    };

    load_stage(0, 0);
    load_stage(1, 1);

    // full stages 0..nS-2 : wait -> barrier -> prefetch s+2 -> compute<4>
    #pragma unroll 1
    for (int s = 0; s < nS - 1; ++s) {
        cp_wait_n(1);
        __syncthreads();
        if (s + 2 < nS) load_stage(s + 2, (s + 2) % 3);
        const int buf = s % 3;
        mma_ks<4>(reinterpret_cast<const __nv_bfloat16*>(dsm) + buf * (128 * 72),
                  reinterpret_cast<const __nv_bfloat16*>(dsm + 3 * STG) + buf * (128 * 72),
                  wm0, wn0, acc);
    }
    // last stage: compile-time trimmed k-steps
    {
        cp_wait_n(0);
        __syncthreads();
        const int buf = (nS - 1) % 3;
        mma_ks<KS_LAST>(reinterpret_cast<const __nv_bfloat16*>(dsm) + buf * (128 * 72),
                        reinterpret_cast<const __nv_bfloat16*>(dsm + 3 * STG) + buf * (128 * 72),
                        wm0, wn0, acc);
    }
    __syncthreads();    // protect smem reuse by epilogue staging

    // ---- fused LSTM epilogue (MUFU tanh) ------------------------------------
    float* stageW = reinterpret_cast<float*>(dsm) + warpI * 320;   // 16x20 per warp
    const int rr = lane >> 1;
    const int cc = (lane & 1) * 8;

    const float* bs = bsum + z * 544;
    float* Csel = z ? Cb : Cf;
    const int hoff = (MODE == 0) ? (z ? 408 : 0) : (z ? 136 : 272);

    #pragma unroll
    for (int i = 0; i < 4; ++i) {
        #pragma unroll
        for (int j = 0; j < 4; ++j) {
            const int cg0 = bn0 + wn0 + j * 16;
            if (cg0 >= GATES) continue;
            wmma::store_matrix_sync(stageW, acc[i][j], 20, wmma::mem_row_major);
            __syncwarp();

            const int b  = bm0 + wm0 + i * 16 + rr;
            const int gc = cg0 + cc;
            float4 v0 = *reinterpret_cast<float4*>(&stageW[rr * 20 + cc]);
            float4 v1 = *reinterpret_cast<float4*>(&stageW[rr * 20 + cc + 4]);
            __syncwarp();

            const float4 b0 = *reinterpret_cast<const float4*>(bs + gc);
            const float4 b1 = *reinterpret_cast<const float4*>(bs + gc + 4);

            #pragma unroll
            for (int q = 0; q < 2; ++q) {
                float4 v  = q ? v1 : v0;
                float4 bb = q ? b1 : b0;
                int j2 = ((gc + q * 4) >> 2);
                float gi = v.x + bb.x;
                float gf = v.y + bb.y;
                float gg = v.z + bb.z;
                float go = v.w + bb.w;
                float c;
                if (MODE == 0) c = fast_sigm(gi) * fast_tanh(gg);
                else           c = fast_sigm(gf) * Csel[(size_t)b * HH + j2]
                                 + fast_sigm(gi) * fast_tanh(gg);
                float h = fast_sigm(go) * fast_tanh(c);
                if (MODE == 0) Csel[(size_t)b * HH + j2] = c;
                Xn[(size_t)b * 544 + hoff + j2] = __float2bfloat16(h);
            }
        }
    }
}

// ---------------- fused head: cooperative, vectorized u_hat -----------------
#define EPB 4
__global__ __launch_bounds__(128 * EPB)
void head_kernel(const __nv_bfloat16* __restrict__ X,
                 const float* __restrict__ conv_w,
                 const float* __restrict__ conv_b,
                 const __nv_bfloat16* __restrict__ Wcb,
                 const float* __restrict__ fc1_w,
                 const float* __restrict__ fc1_b,
                 const float* __restrict__ fc2_w,
                 const float* __restrict__ fc2_b,
                 float* __restrict__ out, int out_size)
{
    extern __shared__ float hsm[];
    float* xs_a    = hsm;
    float* u_a     = xs_a + EPB * 2 * LL;
    float* sred_a  = u_a + EPB * NCAPS * LL;
    float* scale_a = sred_a + EPB * NCAPS * 4;
    float* uhat_a  = scale_a + EPB * NCAPS;
    float* vv_a    = uhat_a + EPB * NCAPS * OUTC;
    float* wred_a  = vv_a + EPB * OUTC;

    const int tid  = threadIdx.x;
    const int e    = tid >> 7;
    const int t    = tid & 127;
    const int lane = tid & 31;
    const int W16  = tid >> 5;
    const int w4   = W16 & 3;
    const int b    = blockIdx.x * EPB + e;
    const __nv_bfloat16* x = X + (size_t)b * 544;

    float* xs    = xs_a    + e * 2 * LL;
    float* u     = u_a     + e * NCAPS * LL;
    float* scale = scale_a + e * NCAPS;
    float* vv    = vv_a    + e * OUTC;
    float* wred  = wred_a  + e * 8;

    for (int i = t; i < 544; i += 128)
        xs[i] = __bfloat162float(x[i]);
    __syncthreads();

    for (int idx = t; idx < NCAPS * LL; idx += 128) {
        int c = idx / LL, k = idx % LL;
        int dd = (c >> 1) + 1, o = c & 1;
        int left = dd >> 1;
        const float* w = conv_w + (size_t)((dd - 1) * 2 + o) * 4;
        float acc = conv_b[(dd - 1) * 2 + o];
        #pragma unroll
        for (int i = 0; i < 2; ++i)
            #pragma unroll
            for (int kk = 0; kk < 2; ++kk) {
                int p = k + kk * dd - left;
                if (p >= 0 && p < LL) acc += w[i * 2 + kk] * xs[i * LL + p];
            }
        u[c * LL + k] = acc;
    }
    __syncthreads();

    #pragma unroll
    for (int c = 0; c < NCAPS; ++c) {
        float q0 = u[c * LL + t];
        float q1 = u[c * LL + t + 128];
        float p  = q0 * q0 + q1 * q1;
        if (t < 16) { float q2 = u[c * LL + t + 256]; p += q2 * q2; }
        #pragma unroll
        for (int off = 16; off > 0; off >>= 1)
            p += __shfl_down_sync(0xffffffffu, p, off);
        if (lane == 0) sred_a[(e * NCAPS + c) * 4 + w4] = p;
    }
    __syncthreads();
    if (t < NCAPS) {
        const float* sr = &sred_a[(e * NCAPS + t) * 4];
        float s2 = sr[0] + sr[1] + sr[2] + sr[3];
        float n = sqrtf(s2);
        scale[t] = (1.f - 1.f / (expf(n) + 1e-20f)) / (n + 1e-20f);
    }
    __syncthreads();

    for (int p = W16; p < NCAPS * OUTC; p += 16) {
        int c = p >> 4;
        const __nv_bfloat162* wr2 =
            reinterpret_cast<const __nv_bfloat162*>(Wcb + (size_t)p * LL);
        const float2* u0 = reinterpret_cast<const float2*>(u_a + 0 * NCAPS * LL + c * LL);
        const float2* u1 = reinterpret_cast<const float2*>(u_a + 1 * NCAPS * LL + c * LL);
        const float2* u2 = reinterpret_cast<const float2*>(u_a + 2 * NCAPS * LL + c * LL);
        const float2* u3 = reinterpret_cast<const float2*>(u_a + 3 * NCAPS * LL + c * LL);
        float a0 = 0.f, a1 = 0.f, a2 = 0.f, a3 = 0.f;
        #pragma unroll
        for (int s = 0; s < 5; ++s) {
            int kp = s * 32 + lane;
            if (kp < LL / 2) {
                float2 w2 = __bfloat1622float2(wr2[kp]);
                float2 q;
                q = u0[kp]; a0 += w2.x * q.x + w2.y * q.y;
                q = u1[kp]; a1 += w2.x * q.x + w2.y * q.y;
                q = u2[kp]; a2 += w2.x * q.x + w2.y * q.y;
                q = u3[kp]; a3 += w2.x * q.x + w2.y * q.y;
            }
        }
        #pragma unroll
        for (int off = 16; off > 0; off >>= 1) {
            a0 += __shfl_down_sync(0xffffffffu, a0, off);
            a1 += __shfl_down_sync(0xffffffffu, a1, off);
            a2 += __shfl_down_sync(0xffffffffu, a2, off);
            a3 += __shfl_down_sync(0xffffffffu, a3, off);
        }
        if (lane == 0) {
            uhat_a[0 * 160 + p] = a0 * scale_a[0 * NCAPS + c];
            uhat_a[1 * 160 + p] = a1 * scale_a[1 * NCAPS + c];
            uhat_a[2 * 160 + p] = a2 * scale_a[2 * NCAPS + c];
            uhat_a[3 * 160 + p] = a3 * scale_a[3 * NCAPS + c];
        }
    }
    __syncthreads();

    if (t < OUTC) {
        float s = 0.f;
        #pragma unroll
        for (int c = 0; c < NCAPS; ++c) s += uhat_a[e * 160 + c * OUTC + t];
        float sq = s * s;
        #pragma unroll
        for (int off = 8; off > 0; off >>= 1)
            sq += __shfl_xor_sync(0x0000ffffu, sq, off);
        float f = sq / (1.f + sq) / sqrtf(sq);
        vv[t] = f * s;
    }
    __syncthreads();

    float p0 = 0.f, p1 = 0.f;
    for (int j = t; j < HH; j += 128) {
        float h = fc1_b[j];
        #pragma unroll
        for (int o = 0; o < OUTC; ++o) h += vv[o] * fc1_w[j * OUTC + o];
        h = fmaxf(h, 0.f);
        p0 += fc2_w[j] * h;
        p1 += fc2_w[HH + j] * h;
    }
    #pragma unroll
    for (int off = 16; off > 0; off >>= 1) {
        p0 += __shfl_down_sync(0xffffffffu, p0, off);
        p1 += __shfl_down_sync(0xffffffffu, p1, off);
    }
    if (lane == 0) { wred[w4 * 2 + 0] = p0; wred[w4 * 2 + 1] = p1; }
    __syncthreads();

    if (t == 0) {
        float l0 = fc2_b[0], l1 = fc2_b[1];
        #pragma unroll
        for (int ww = 0; ww < 4; ++ww) { l0 += wred[ww * 2 + 0]; l1 += wred[ww * 2 + 1]; }
        out[(size_t)b * 2 + 0] = l0;
        out[(size_t)b * 2 + 1] = l1;
        if (out_size >= 4 * BATCH) {
            float m = fmaxf(l0, l1);
            float e0 = expf(l0 - m), e1 = expf(l1 - m);
            float den = e0 + e1;
            out[(size_t)2 * BATCH + b * 2 + 0] = e0 / den;
            out[(size_t)2 * BATCH + b * 2 + 1] = e1 / den;
        }
    }
}

// ---------------- launch ----------------------------------------------------
extern "C" void kernel_launch(void* const* d_in, const int* in_sizes, int n_in,
                              void* d_out, int out_size)
{
    const int*   seq    = (const int*)  d_in[0];
    const float* sig    = (const float*)d_in[1];
    const float* embed  = (const float*)d_in[2];
    const float* w_ih   = (const float*)d_in[3];
    const float* w_hh   = (const float*)d_in[4];
    const float* b_ih   = (const float*)d_in[5];
    const float* b_hh   = (const float*)d_in[6];
    const float* conv_w = (const float*)d_in[7];
    const float* conv_b = (const float*)d_in[8];
    const float* W_caps = (const float*)d_in[9];
    const float* fc1_w  = (const float*)d_in[10];
    const float* fc1_b  = (const float*)d_in[11];
    const float* fc2_w  = (const float*)d_in[12];
    const float* fc2_b  = (const float*)d_in[13];
    float* out = (float*)d_out;

    __nv_bfloat16 *X0, *X1, *Wcat, *Wcb;
    float *Cf, *Cb, *Bsum;
    cudaGetSymbolAddress((void**)&X0,   g_Xb0);
    cudaGetSymbolAddress((void**)&X1,   g_Xb1);
    cudaGetSymbolAddress((void**)&Cf,   g_Cf);
    cudaGetSymbolAddress((void**)&Cb,   g_Cb);
    cudaGetSymbolAddress((void**)&Wcat, g_Wcat);
    cudaGetSymbolAddress((void**)&Bsum, g_Bs);
    cudaGetSymbolAddress((void**)&Wcb,  g_Wcb);
    __nv_bfloat16* Xs[2] = {X0, X1};

    const int SMEM_G = 3 * 128 * 72 * 2 * 2;     // 110592
    const int SMEM_H = (EPB * (2*LL + NCAPS*LL + NCAPS*4 + NCAPS + NCAPS*OUTC + OUTC + 8)) * 4;
    cudaFuncSetAttribute(gemm_lstm<272, 0>,
                         cudaFuncAttributeMaxDynamicSharedMemorySize, SMEM_G);
    cudaFuncSetAttribute(gemm_lstm<408, 1>,
                         cudaFuncAttributeMaxDynamicSharedMemorySize, SMEM_G);
    cudaFuncSetAttribute(head_kernel,
                         cudaFuncAttributeMaxDynamicSharedMemorySize, SMEM_H);

    const long long nSetup = (long long)BATCH * LL + (long long)NL * 2 * GATES * KCAT
                           + NL * GCOLS + NCAPS * OUTC * LL;
    setup_kernel<<<(int)((nSetup + 255) / 256), 256>>>(
        seq, sig, embed, w_ih, w_hh, b_ih, b_hh, W_caps, X0, Wcat, Bsum, Wcb);

    dim3 grid(5, BATCH / 128, 2);
    for (int l = 0; l < NL; ++l) {
        __nv_bfloat16* Xc = Xs[l & 1];
        __nv_bfloat16* Xn = Xs[(l + 1) & 1];
        const __nv_bfloat16* Wl = Wcat + (size_t)l * 2 * GATES * KCAT;
        const float* Bl = Bsum + (size_t)l * GCOLS;

        gemm_lstm<272, 0><<<grid, 128, SMEM_G>>>(Xc, Wl, Bl, Xn, Cf, Cb);
        gemm_lstm<408, 1><<<grid, 128, SMEM_G>>>(Xc, Wl, Bl, Xn, Cf, Cb);
    }

    head_kernel<<<BATCH / EPB, 128 * EPB, SMEM_H>>>(X1, conv_w, conv_b, Wcb,
                                                    fc1_w, fc1_b, fc2_w, fc2_b,
                                                    out, out_size);
}

// round 17
// speedup vs baseline: 1.3071x; 1.1462x over previous
#include <cuda_runtime.h>
#include <cuda_bf16.h>
#include <mma.h>
#include <cstdint>

using namespace nvcuda;

// ---------------- problem constants ----------------
#define BATCH   16384
#define KMER    17
#define HH      136
#define LL      272
#define GATES   544
#define GCOLS   1088
#define NL      3
#define OUTC    16
#define NCAPS   10
#define KCAT    408           // 272 + 136 concatenated K
#define KCAPS   2720          // NCAPS * LL

// ---------------- device scratch --------------------------------------------
__device__ __align__(256) __nv_bfloat16 g_Xb0[(size_t)BATCH * 2 * LL];
__device__ __align__(256) __nv_bfloat16 g_Xb1[(size_t)BATCH * 2 * LL];
__device__ __align__(256) float         g_Cf [(size_t)BATCH * HH];
__device__ __align__(256) float         g_Cb [(size_t)BATCH * HH];
__device__ __align__(256) __nv_bfloat16 g_Wcat[(size_t)NL * 2 * GATES * KCAT];
__device__ __align__(256) float         g_Bs [(size_t)NL * GCOLS];
__device__ __align__(256) __nv_bfloat16 g_Wcr[(size_t)OUTC * KCAPS];      // reshaped W_caps
__device__ __align__(256) __nv_bfloat16 g_Y  [(size_t)BATCH * KCAPS];     // scaled caps (89MB)
__device__ __align__(256) float         g_S  [(size_t)BATCH * OUTC];      // s = sum_c u_hat

// ---------------- fast transcendentals (MUFU tanh, sm_75+) -------------------
__device__ __forceinline__ float fast_tanh(float x) {
    float r;
    asm("tanh.approx.f32 %0, %1;" : "=f"(r) : "f"(x));
    return r;
}
__device__ __forceinline__ float fast_sigm(float x) {
    return fmaf(fast_tanh(0.5f * x), 0.5f, 0.5f);
}

__device__ __forceinline__ uint32_t smem_u32(const void* p) {
    uint32_t a;
    asm("{ .reg .u64 t; cvta.to.shared.u64 t, %1; cvt.u32.u64 %0, t; }" : "=r"(a) : "l"(p));
    return a;
}
__device__ __forceinline__ void cp16(uint32_t smaddr, const void* g, int sb) {
    asm volatile("cp.async.cg.shared.global [%0], [%1], 16, %2;\n"
                 :: "r"(smaddr), "l"(g), "r"(sb));
}
__device__ __forceinline__ void cp_wait_n(int n) {
    if (n <= 0)      asm volatile("cp.async.wait_group 0;");
    else             asm volatile("cp.async.wait_group 1;");
}

// ---------------- setup: prep input + all weight conversions (1 launch) -----
__global__ void setup_kernel(const int* __restrict__ seq,
                             const float* __restrict__ sig,
                             const float* __restrict__ embed,
                             const float* __restrict__ wih,
                             const float* __restrict__ whh,
                             const float* __restrict__ bih,
                             const float* __restrict__ bhh,
                             const float* __restrict__ wcaps,
                             __nv_bfloat16* __restrict__ X,
                             __nv_bfloat16* __restrict__ wcat,
                             float* __restrict__ bsum,
                             __nv_bfloat16* __restrict__ wcr)
{
    const long long nPrep = (long long)BATCH * LL;
    const long long nW    = (long long)NL * 2 * GATES * KCAT;
    const long long nB    = NL * GCOLS;
    const long long nC    = OUTC * KCAPS;
    long long i = (long long)blockIdx.x * blockDim.x + threadIdx.x;

    if (i < nPrep) {
        int b = (int)(i / LL), r = (int)(i % LL);
        int p = r >> 4, e = r & 15;
        int tok = seq[b * KMER + p];
        X[(size_t)b * 544 + r]       = __float2bfloat16(embed[tok * 16 + e]);
        X[(size_t)b * 544 + 272 + r] = __float2bfloat16(sig[(size_t)b * LL + r]);
        return;
    }
    i -= nPrep;
    if (i < nW) {
        const int per = GATES * KCAT;
        int ld = (int)(i / per);  int r = (int)(i % per);
        int n = r / KCAT, k = r % KCAT;
        int j = n >> 2, g = n & 3;
        float v = (k < 272)
            ? wih[((size_t)ld * GATES + g * HH + j) * LL + k]
            : whh[((size_t)ld * GATES + g * HH + j) * HH + (k - 272)];
        wcat[i] = __float2bfloat16(v);
        return;
    }
    i -= nW;
    if (i < nB) {
        int l = (int)(i / GCOLS); int np = (int)(i % GCOLS);
        int d = np / GATES, q = np % GATES;
        int j = q >> 2, g = q & 3;
        int src = (l * 2 + d) * GATES + g * HH + j;
        bsum[i] = bih[src] + bhh[src];
        return;
    }
    i -= nB;
    if (i < nC) {
        // wcr[o][c*272+k] = wcaps[c][o][k]
        int o = (int)(i / KCAPS); int r = (int)(i % KCAPS);
        int c = r / LL, k = r % LL;
        wcr[i] = __float2bfloat16(wcaps[((size_t)c * OUTC + o) * LL + k]);
    }
}

// ---------------- compute KS k-steps of one 64-K stage (64x64 warp tile) -----
template<int KS>
__device__ __forceinline__ void mma_ks(const __nv_bfloat16* __restrict__ Ab,
                                       const __nv_bfloat16* __restrict__ Bb,
                                       int wm0, int wn0,
                                       wmma::fragment<wmma::accumulator, 16, 16, 16, float> (&acc)[4][4])
{
    #pragma unroll
    for (int ks = 0; ks < KS; ++ks) {
        const int kk = ks * 16;
        wmma::fragment<wmma::matrix_a, 16, 16, 16, __nv_bfloat16, wmma::row_major> af[4];
        wmma::fragment<wmma::matrix_b, 16, 16, 16, __nv_bfloat16, wmma::col_major> bfr[4];
        #pragma unroll
        for (int i = 0; i < 4; ++i)
            wmma::load_matrix_sync(af[i], Ab + (wm0 + i * 16) * 72 + kk, 72);
        #pragma unroll
        for (int j = 0; j < 4; ++j)
            wmma::load_matrix_sync(bfr[j], Bb + (wn0 + j * 16) * 72 + kk, 72);
        #pragma unroll
        for (int i = 0; i < 4; ++i)
            #pragma unroll
            for (int j = 0; j < 4; ++j)
                wmma::mma_sync(acc[i][j], af[i], bfr[j], acc[i][j]);
    }
}

// ---------------- fused LSTM GEMM (wmma bf16, NT, 3-stage ring) --------------
template<int KACT, int MODE>
__global__ __launch_bounds__(128, 2)
void gemm_lstm(const __nv_bfloat16* __restrict__ Xc,
               const __nv_bfloat16* __restrict__ Wcat,
               const float* __restrict__ bsum,
               __nv_bfloat16* __restrict__ Xn,
               float* __restrict__ Cf, float* __restrict__ Cb)
{
    extern __shared__ __align__(16) char dsm[];
    const int STG = 128 * 72 * 2;          // 18432 B per stage per matrix

    const int tid   = threadIdx.x;
    const int warpI = tid >> 5;            // 0..3
    const int lane  = tid & 31;
    const int z     = blockIdx.z;
    const int bm0   = blockIdx.y * 128;
    const int bn0   = blockIdx.x * 128;
    const int wm0   = (warpI & 1) * 64;
    const int wn0   = (warpI >> 1) * 64;

    const uint32_t smA = smem_u32(dsm);
    const uint32_t smB = smA + 3 * STG;

    const __nv_bfloat16* A1 = Xc + (MODE == 0 ? z * 272 : (1 - z) * 272);
    const __nv_bfloat16* A2 = Xn + z * 408;
    const __nv_bfloat16* Bsrc = Wcat + (size_t)z * GATES * KCAT;

    wmma::fragment<wmma::accumulator, 16, 16, 16, float> acc[4][4];
    #pragma unroll
    for (int i = 0; i < 4; ++i)
        #pragma unroll
        for (int j = 0; j < 4; ++j)
            wmma::fill_fragment(acc[i][j], 0.0f);

    constexpr int nS      = (KACT + 63) >> 6;
    constexpr int KS_LAST = (KACT - (nS - 1) * 64 + 15) >> 4;

    auto load_stage = [&](int s, int buf) {
        const int k0 = s * 64;
        #pragma unroll
        for (int it = 0; it < 8; ++it) {
            int c   = tid + it * 128;
            int row = c >> 3;
            int kc  = (c & 7) * 8;
            int kg  = k0 + kc;
            bool kv = kg < KACT;
            const __nv_bfloat16* ap;
            if (MODE == 0 || kg < 272)
                ap = A1 + (size_t)(bm0 + row) * 544 + (kv ? kg : 0);
            else
                ap = A2 + (size_t)(bm0 + row) * 544 + (kv ? (kg - 272) : 0);
            cp16(smA + buf * STG + row * 144 + kc * 2, ap, kv ? 16 : 0);
            int n   = bn0 + row;
            bool bok = kv && (n < GATES);
            const __nv_bfloat16* bp = Bsrc + (size_t)(n < GATES ? n : 0) * KCAT
                                           + (kv ? kg : 0);
            cp16(smB + buf * STG + row * 144 + kc * 2, bp, bok ? 16 : 0);
        }
        asm volatile("cp.async.commit_group;\n");
    };

    load_stage(0, 0);
    load_stage(1, 1);

    #pragma unroll 1
    for (int s = 0; s < nS - 1; ++s) {
        cp_wait_n(1);
        __syncthreads();
        if (s + 2 < nS) load_stage(s + 2, (s + 2) % 3);
        const int buf = s % 3;
        mma_ks<4>(reinterpret_cast<const __nv_bfloat16*>(dsm) + buf * (128 * 72),
                  reinterpret_cast<const __nv_bfloat16*>(dsm + 3 * STG) + buf * (128 * 72),
                  wm0, wn0, acc);
    }
    {
        cp_wait_n(0);
        __syncthreads();
        const int buf = (nS - 1) % 3;
        mma_ks<KS_LAST>(reinterpret_cast<const __nv_bfloat16*>(dsm) + buf * (128 * 72),
                        reinterpret_cast<const __nv_bfloat16*>(dsm + 3 * STG) + buf * (128 * 72),
                        wm0, wn0, acc);
    }
    __syncthreads();

    // ---- fused LSTM epilogue (MUFU tanh) ------------------------------------
    float* stageW = reinterpret_cast<float*>(dsm) + warpI * 320;
    const int rr = lane >> 1;
    const int cc = (lane & 1) * 8;

    const float* bs = bsum + z * 544;
    float* Csel = z ? Cb : Cf;
    const int hoff = (MODE == 0) ? (z ? 408 : 0) : (z ? 136 : 272);

    #pragma unroll
    for (int i = 0; i < 4; ++i) {
        #pragma unroll
        for (int j = 0; j < 4; ++j) {
            const int cg0 = bn0 + wn0 + j * 16;
            if (cg0 >= GATES) continue;
            wmma::store_matrix_sync(stageW, acc[i][j], 20, wmma::mem_row_major);
            __syncwarp();

            const int b  = bm0 + wm0 + i * 16 + rr;
            const int gc = cg0 + cc;
            float4 v0 = *reinterpret_cast<float4*>(&stageW[rr * 20 + cc]);
            float4 v1 = *reinterpret_cast<float4*>(&stageW[rr * 20 + cc + 4]);
            __syncwarp();

            const float4 b0 = *reinterpret_cast<const float4*>(bs + gc);
            const float4 b1 = *reinterpret_cast<const float4*>(bs + gc + 4);

            #pragma unroll
            for (int q = 0; q < 2; ++q) {
                float4 v  = q ? v1 : v0;
                float4 bb = q ? b1 : b0;
                int j2 = ((gc + q * 4) >> 2);
                float gi = v.x + bb.x;
                float gf = v.y + bb.y;
                float gg = v.z + bb.z;
                float go = v.w + bb.w;
                float c;
                if (MODE == 0) c = fast_sigm(gi) * fast_tanh(gg);
                else           c = fast_sigm(gf) * Csel[(size_t)b * HH + j2]
                                 + fast_sigm(gi) * fast_tanh(gg);
                float h = fast_sigm(go) * fast_tanh(c);
                if (MODE == 0) Csel[(size_t)b * HH + j2] = c;
                Xn[(size_t)b * 544 + hoff + j2] = __float2bfloat16(h);
            }
        }
    }
}

// ---------------- head stage 1: conv + norm + scale -> Y (bf16) --------------
#define EPB 4
__global__ __launch_bounds__(128 * EPB)
void conv_norm_kernel(const __nv_bfloat16* __restrict__ X,
                      const float* __restrict__ conv_w,
                      const float* __restrict__ conv_b,
                      __nv_bfloat16* __restrict__ Y)
{
    extern __shared__ float hsm[];
    float* xs_a    = hsm;                          // 4*544
    float* u_a     = xs_a + EPB * 2 * LL;          // 4*2720
    float* sred_a  = u_a + EPB * NCAPS * LL;       // 4*40
    float* scale_a = sred_a + EPB * NCAPS * 4;     // 4*10

    const int tid  = threadIdx.x;
    const int e    = tid >> 7;
    const int t    = tid & 127;
    const int lane = tid & 31;
    const int w4   = (tid >> 5) & 3;
    const int b    = blockIdx.x * EPB + e;
    const __nv_bfloat16* x = X + (size_t)b * 544;

    float* xs    = xs_a    + e * 2 * LL;
    float* u     = u_a     + e * NCAPS * LL;
    float* scale = scale_a + e * NCAPS;

    for (int i = t; i < 544; i += 128)
        xs[i] = __bfloat162float(x[i]);
    __syncthreads();

    for (int idx = t; idx < NCAPS * LL; idx += 128) {
        int c = idx / LL, k = idx % LL;
        int dd = (c >> 1) + 1, o = c & 1;
        int left = dd >> 1;
        const float* w = conv_w + (size_t)((dd - 1) * 2 + o) * 4;
        float acc = conv_b[(dd - 1) * 2 + o];
        #pragma unroll
        for (int i = 0; i < 2; ++i)
            #pragma unroll
            for (int kk = 0; kk < 2; ++kk) {
                int p = k + kk * dd - left;
                if (p >= 0 && p < LL) acc += w[i * 2 + kk] * xs[i * LL + p];
            }
        u[c * LL + k] = acc;
    }
    __syncthreads();

    #pragma unroll
    for (int c = 0; c < NCAPS; ++c) {
        float q0 = u[c * LL + t];
        float q1 = u[c * LL + t + 128];
        float p  = q0 * q0 + q1 * q1;
        if (t < 16) { float q2 = u[c * LL + t + 256]; p += q2 * q2; }
        #pragma unroll
        for (int off = 16; off > 0; off >>= 1)
            p += __shfl_down_sync(0xffffffffu, p, off);
        if (lane == 0) sred_a[(e * NCAPS + c) * 4 + w4] = p;
    }
    __syncthreads();
    if (t < NCAPS) {
        const float* sr = &sred_a[(e * NCAPS + t) * 4];
        float s2 = sr[0] + sr[1] + sr[2] + sr[3];
        float n = sqrtf(s2);
        scale[t] = (1.f - 1.f / (expf(n) + 1e-20f)) / (n + 1e-20f);
    }
    __syncthreads();

    // write Y[b, c*272+k] = bf16(u * scale[c])  (coalesced)
    __nv_bfloat16* yb = Y + (size_t)b * KCAPS;
    for (int idx = t; idx < KCAPS; idx += 128) {
        int c = idx / LL;
        yb[idx] = __float2bfloat16(u[idx] * scale[c]);
    }
}

// ---------------- head stage 2: S(16384,16) = Y(16384,2720) @ Wr(16,2720)^T --
// 3-stage ring (same validated structure as gemm_lstm) — NO live-buffer writes.
__global__ __launch_bounds__(128, 2)
void gemm_caps(const __nv_bfloat16* __restrict__ Y,
               const __nv_bfloat16* __restrict__ Wr,
               float* __restrict__ S)
{
    extern __shared__ __align__(16) char dsm[];
    const int STG_A = 128 * 72 * 2;        // 18432 B per stage
    const int STG_B = 16 * 72 * 2;         // 2304 B per stage

    const int tid   = threadIdx.x;
    const int warpI = tid >> 5;            // 0..3, wm0 = warpI*32
    const int lane  = tid & 31;
    const int bm0   = blockIdx.x * 128;
    const int wm0   = warpI * 32;

    const uint32_t smA = smem_u32(dsm);
    const uint32_t smB = smA + 3 * STG_A;

    wmma::fragment<wmma::accumulator, 16, 16, 16, float> acc[2];
    wmma::fill_fragment(acc[0], 0.0f);
    wmma::fill_fragment(acc[1], 0.0f);

    constexpr int nS      = (KCAPS + 63) >> 6;                 // 43
    constexpr int KS_LAST = (KCAPS - (nS - 1) * 64 + 15) >> 4; // 2

    auto load_stage = [&](int s, int buf) {
        const int k0 = s * 64;
        #pragma unroll
        for (int it = 0; it < 8; ++it) {
            int c   = tid + it * 128;
            int row = c >> 3;
            int kc  = (c & 7) * 8;
            int kg  = k0 + kc;
            bool kv = kg < KCAPS;
            cp16(smA + buf * STG_A + row * 144 + kc * 2,
                 Y + (size_t)(bm0 + row) * KCAPS + (kv ? kg : 0), kv ? 16 : 0);
        }
        {   // B tile: 16 rows x 8 chunks = 128 threads
            int row = tid >> 3;
            int kc  = (tid & 7) * 8;
            int kg  = k0 + kc;
            bool kv = kg < KCAPS;
            cp16(smB + buf * STG_B + row * 144 + kc * 2,
                 Wr + (size_t)row * KCAPS + (kv ? kg : 0), kv ? 16 : 0);
        }
        asm volatile("cp.async.commit_group;\n");
    };

    auto compute = [&](int buf, int KS) {
        const __nv_bfloat16* Ab = reinterpret_cast<const __nv_bfloat16*>(dsm) + buf * (128 * 72);
        const __nv_bfloat16* Bb = reinterpret_cast<const __nv_bfloat16*>(dsm + 3 * STG_A) + buf * (16 * 72);
        #pragma unroll
        for (int ks = 0; ks < 4; ++ks) {
            if (ks >= KS) break;
            const int kk = ks * 16;
            wmma::fragment<wmma::matrix_a, 16, 16, 16, __nv_bfloat16, wmma::row_major> af[2];
            wmma::fragment<wmma::matrix_b, 16, 16, 16, __nv_bfloat16, wmma::col_major> bfr;
            wmma::load_matrix_sync(af[0], Ab + (wm0 + 0) * 72 + kk, 72);
            wmma::load_matrix_sync(af[1], Ab + (wm0 + 16) * 72 + kk, 72);
            wmma::load_matrix_sync(bfr, Bb + kk, 72);
            wmma::mma_sync(acc[0], af[0], bfr, acc[0]);
            wmma::mma_sync(acc[1], af[1], bfr, acc[1]);
        }
    };

    load_stage(0, 0);
    load_stage(1, 1);

    #pragma unroll 1
    for (int s = 0; s < nS - 1; ++s) {
        cp_wait_n(1);
        __syncthreads();
        if (s + 2 < nS) load_stage(s + 2, (s + 2) % 3);   // never the live buffer
        compute(s % 3, 4);
    }
    {
        cp_wait_n(0);
        __syncthreads();
        compute((nS - 1) % 3, KS_LAST);
    }
    __syncthreads();   // before smem reuse by epilogue staging

    // epilogue: write S
    float* stageW = reinterpret_cast<float*>(dsm) + warpI * 320;
    const int rr = lane >> 1;
    const int cc = (lane & 1) * 8;
    #pragma unroll
    for (int i = 0; i < 2; ++i) {
        wmma::store_matrix_sync(stageW, acc[i], 20, wmma::mem_row_major);
        __syncwarp();
        const int b = bm0 + wm0 + i * 16 + rr;
        float4 v0 = *reinterpret_cast<float4*>(&stageW[rr * 20 + cc]);
        float4 v1 = *reinterpret_cast<float4*>(&stageW[rr * 20 + cc + 4]);
        __syncwarp();
        *reinterpret_cast<float4*>(&S[(size_t)b * OUTC + cc])     = v0;
        *reinterpret_cast<float4*>(&S[(size_t)b * OUTC + cc + 4]) = v1;
    }
}

// ---------------- head stage 3: squash + fc1 + fc2 + softmax -----------------
__global__ __launch_bounds__(256)
void caps_tail(const float* __restrict__ S,
               const float* __restrict__ fc1_w,
               const float* __restrict__ fc1_b,
               const float* __restrict__ fc2_w,
               const float* __restrict__ fc2_b,
               float* __restrict__ out, int out_size)
{
    __shared__ float vsm[8][OUTC];
    const int lane = threadIdx.x & 31;
    const int w    = threadIdx.x >> 5;          // 0..7
    const int b    = blockIdx.x * 8 + w;

    float sv = (lane < OUTC) ? S[(size_t)b * OUTC + lane] : 0.f;
    float sq = sv * sv;
    #pragma unroll
    for (int off = 8; off > 0; off >>= 1)
        sq += __shfl_xor_sync(0xffffffffu, sq, off);
    float f = sq / (1.f + sq) / sqrtf(sq);
    if (lane < OUTC) vsm[w][lane] = f * sv;
    __syncwarp();

    float p0 = 0.f, p1 = 0.f;
    for (int j = lane; j < HH; j += 32) {
        float h = fc1_b[j];
        #pragma unroll
        for (int o = 0; o < OUTC; ++o) h += vsm[w][o] * fc1_w[j * OUTC + o];
        h = fmaxf(h, 0.f);
        p0 += fc2_w[j] * h;
        p1 += fc2_w[HH + j] * h;
    }
    #pragma unroll
    for (int off = 16; off > 0; off >>= 1) {
        p0 += __shfl_down_sync(0xffffffffu, p0, off);
        p1 += __shfl_down_sync(0xffffffffu, p1, off);
    }
    if (lane == 0) {
        float l0 = p0 + fc2_b[0], l1 = p1 + fc2_b[1];
        out[(size_t)b * 2 + 0] = l0;
        out[(size_t)b * 2 + 1] = l1;
        if (out_size >= 4 * BATCH) {
            float m = fmaxf(l0, l1);
            float e0 = expf(l0 - m), e1 = expf(l1 - m);
            float den = e0 + e1;
            out[(size_t)2 * BATCH + b * 2 + 0] = e0 / den;
            out[(size_t)2 * BATCH + b * 2 + 1] = e1 / den;
        }
    }
}

// ---------------- launch ----------------------------------------------------
extern "C" void kernel_launch(void* const* d_in, const int* in_sizes, int n_in,
                              void* d_out, int out_size)
{
    const int*   seq    = (const int*)  d_in[0];
    const float* sig    = (const float*)d_in[1];
    const float* embed  = (const float*)d_in[2];
    const float* w_ih   = (const float*)d_in[3];
    const float* w_hh   = (const float*)d_in[4];
    const float* b_ih   = (const float*)d_in[5];
    const float* b_hh   = (const float*)d_in[6];
    const float* conv_w = (const float*)d_in[7];
    const float* conv_b = (const float*)d_in[8];
    const float* W_caps = (const float*)d_in[9];
    const float* fc1_w  = (const float*)d_in[10];
    const float* fc1_b  = (const float*)d_in[11];
    const float* fc2_w  = (const float*)d_in[12];
    const float* fc2_b  = (const float*)d_in[13];
    float* out = (float*)d_out;

    __nv_bfloat16 *X0, *X1, *Wcat, *Wcr, *Y;
    float *Cf, *Cb, *Bsum, *S;
    cudaGetSymbolAddress((void**)&X0,   g_Xb0);
    cudaGetSymbolAddress((void**)&X1,   g_Xb1);
    cudaGetSymbolAddress((void**)&Cf,   g_Cf);
    cudaGetSymbolAddress((void**)&Cb,   g_Cb);
    cudaGetSymbolAddress((void**)&Wcat, g_Wcat);
    cudaGetSymbolAddress((void**)&Bsum, g_Bs);
    cudaGetSymbolAddress((void**)&Wcr,  g_Wcr);
    cudaGetSymbolAddress((void**)&Y,    g_Y);
    cudaGetSymbolAddress((void**)&S,    g_S);
    __nv_bfloat16* Xs[2] = {X0, X1};

    const int SMEM_G = 3 * 128 * 72 * 2 * 2;                       // 110592
    const int SMEM_C = (EPB * (2*LL + NCAPS*LL + NCAPS*4 + NCAPS)) * 4;
    const int SMEM_P = 3 * (128 * 72 * 2 + 16 * 72 * 2);           // 62208
    cudaFuncSetAttribute(gemm_lstm<272, 0>,
                         cudaFuncAttributeMaxDynamicSharedMemorySize, SMEM_G);
    cudaFuncSetAttribute(gemm_lstm<408, 1>,
                         cudaFuncAttributeMaxDynamicSharedMemorySize, SMEM_G);
    cudaFuncSetAttribute(conv_norm_kernel,
                         cudaFuncAttributeMaxDynamicSharedMemorySize, SMEM_C);
    cudaFuncSetAttribute(gemm_caps,
                         cudaFuncAttributeMaxDynamicSharedMemorySize, SMEM_P);

    const long long nSetup = (long long)BATCH * LL + (long long)NL * 2 * GATES * KCAT
                           + NL * GCOLS + OUTC * KCAPS;
    setup_kernel<<<(int)((nSetup + 255) / 256), 256>>>(
        seq, sig, embed, w_ih, w_hh, b_ih, b_hh, W_caps, X0, Wcat, Bsum, Wcr);

    dim3 grid(5, BATCH / 128, 2);
    for (int l = 0; l < NL; ++l) {
        __nv_bfloat16* Xc = Xs[l & 1];
        __nv_bfloat16* Xn = Xs[(l + 1) & 1];
        const __nv_bfloat16* Wl = Wcat + (size_t)l * 2 * GATES * KCAT;
        const float* Bl = Bsum + (size_t)l * GCOLS;

        gemm_lstm<272, 0><<<grid, 128, SMEM_G>>>(Xc, Wl, Bl, Xn, Cf, Cb);
        gemm_lstm<408, 1><<<grid, 128, SMEM_G>>>(Xc, Wl, Bl, Xn, Cf, Cb);
    }

    conv_norm_kernel<<<BATCH / EPB, 128 * EPB, SMEM_C>>>(X1, conv_w, conv_b, Y);
    gemm_caps<<<BATCH / 128, 128, SMEM_P>>>(Y, Wcr, S);
    caps_tail<<<BATCH / 8, 256>>>(S, fc1_w, fc1_b, fc2_w, fc2_b, out, out_size);
}